// round 9
// baseline (speedup 1.0000x reference)
#include <cuda_runtime.h>
#include <cuda_bf16.h>
#include <cstdint>
#include <cstddef>

#define BB 8
#define SS 1024
#define EE 1024
#define HH 16
#define DD 64
#define NEG_INF (-3.402823466e38f)

// ---------------- scratch (no allocations allowed) ----------------
__device__ __nv_bfloat16 g_Xhi[BB * SS * EE];   // query split
__device__ __nv_bfloat16 g_Xlo[BB * SS * EE];
__device__ __nv_bfloat16 g_Qhi[BB * SS * EE];   // projected q/k/v splits
__device__ __nv_bfloat16 g_Qlo[BB * SS * EE];
__device__ __nv_bfloat16 g_Khi[BB * SS * EE];
__device__ __nv_bfloat16 g_Klo[BB * SS * EE];
__device__ __nv_bfloat16 g_Vhi[BB * SS * EE];
__device__ __nv_bfloat16 g_Vlo[BB * SS * EE];
__device__ __nv_bfloat16 g_AThi[BB * SS * EE];  // attention output split
__device__ __nv_bfloat16 g_ATlo[BB * SS * EE];
__device__ __nv_bfloat16 g_Whi[4][EE * EE];     // Wq,Wk,Wv,Wo splits
__device__ __nv_bfloat16 g_Wlo[4][EE * EE];
__device__ float g_maskflag[BB * SS];
__device__ int   g_mask_dtype;

// ---------------- helpers ----------------
__device__ __forceinline__ uint32_t smem_u32(const void* p) {
    uint32_t a;
    asm("{ .reg .u64 t; cvta.to.shared.u64 t, %1; cvt.u32.u64 %0, t; }" : "=r"(a) : "l"(p));
    return a;
}
__device__ __forceinline__ void ldsm4(uint32_t* r, uint32_t addr) {
    asm volatile("ldmatrix.sync.aligned.m8n8.x4.shared.b16 {%0,%1,%2,%3}, [%4];"
        : "=r"(r[0]), "=r"(r[1]), "=r"(r[2]), "=r"(r[3]) : "r"(addr));
}
__device__ __forceinline__ void ldsm4t(uint32_t* r, uint32_t addr) {
    asm volatile("ldmatrix.sync.aligned.m8n8.x4.trans.shared.b16 {%0,%1,%2,%3}, [%4];"
        : "=r"(r[0]), "=r"(r[1]), "=r"(r[2]), "=r"(r[3]) : "r"(addr));
}
__device__ __forceinline__ void mma16816(float* c, const uint32_t* a, uint32_t b0, uint32_t b1) {
    asm volatile(
        "mma.sync.aligned.m16n8k16.row.col.f32.bf16.bf16.f32 "
        "{%0,%1,%2,%3}, {%4,%5,%6,%7}, {%8,%9}, {%0,%1,%2,%3};"
        : "+f"(c[0]), "+f"(c[1]), "+f"(c[2]), "+f"(c[3])
        : "r"(a[0]), "r"(a[1]), "r"(a[2]), "r"(a[3]), "r"(b0), "r"(b1));
}
__device__ __forceinline__ void cpa16(uint32_t saddr, const void* g) {
    asm volatile("cp.async.cg.shared.global [%0], [%1], 16;" :: "r"(saddr), "l"(g));
}
#define CP_COMMIT() asm volatile("cp.async.commit_group;" ::: "memory")
#define CP_WAIT(n)  asm volatile("cp.async.wait_group %0;" :: "n"(n) : "memory")

__device__ __forceinline__ uint32_t pack_hi2(float x, float y) {
    __nv_bfloat162 v = __halves2bfloat162(__float2bfloat16(x), __float2bfloat16(y));
    return *(uint32_t*)&v;
}
__device__ __forceinline__ uint32_t pack_lo2(float x, float y, uint32_t hi) {
    __nv_bfloat162 h = *(__nv_bfloat162*)&hi;
    __nv_bfloat162 v = __halves2bfloat162(
        __float2bfloat16(x - __bfloat162float(h.x)),
        __float2bfloat16(y - __bfloat162float(h.y)));
    return *(uint32_t*)&v;
}

// ---------------- fp32 -> bf16 hi/lo split ----------------
__global__ void split_kernel(const float* __restrict__ src,
                             __nv_bfloat16* __restrict__ hi,
                             __nv_bfloat16* __restrict__ lo, int n4) {
    int i = blockIdx.x * blockDim.x + threadIdx.x;
    if (i >= n4) return;
    float4 v = ((const float4*)src)[i];
    float vv[4] = {v.x, v.y, v.z, v.w};
    __nv_bfloat16 h[4], l[4];
    #pragma unroll
    for (int j = 0; j < 4; ++j) {
        h[j] = __float2bfloat16(vv[j]);
        l[j] = __float2bfloat16(vv[j] - __bfloat162float(h[j]));
    }
    __nv_bfloat162* ph = (__nv_bfloat162*)&hi[(size_t)i * 4];
    __nv_bfloat162* pl = (__nv_bfloat162*)&lo[(size_t)i * 4];
    ph[0] = __halves2bfloat162(h[0], h[1]);
    ph[1] = __halves2bfloat162(h[2], h[3]);
    pl[0] = __halves2bfloat162(l[0], l[1]);
    pl[1] = __halves2bfloat162(l[2], l[3]);
}

// ---------------- key_padding_mask dtype detection ----------------
__global__ void detect_mask_kernel(const void* mask) {
    const unsigned int* w = (const unsigned int*)mask;
    __shared__ int s_f32, s_big;
    if (threadIdx.x == 0) { s_f32 = 0; s_big = 0; }
    __syncthreads();
    int lf = 0, lb = 0;
    for (int i = threadIdx.x; i < 2048; i += blockDim.x) {
        unsigned int v = w[i];
        if (v == 0x3F800000u) lf = 1;
        else if (v > 1u) lb = 1;
    }
    if (lf) atomicOr(&s_f32, 1);
    if (lb) atomicOr(&s_big, 1);
    __syncthreads();
    if (threadIdx.x == 0)
        g_mask_dtype = s_f32 ? 2 : (s_big ? 0 : 1);
}

__global__ void expand_mask_kernel(const void* mask) {
    int i = blockIdx.x * blockDim.x + threadIdx.x;
    if (i >= BB * SS) return;
    int dt = g_mask_dtype;
    bool f;
    if (dt == 0)      f = ((const unsigned char*)mask)[i] != 0;
    else if (dt == 1) f = ((const int*)mask)[i] != 0;
    else              f = ((const float*)mask)[i] != 0.0f;
    g_maskflag[i] = f ? 1.0f : 0.0f;
}

// ---------------- mma.sync GEMM: C = alpha*(A@W^T + bias) ----------------
// 3-term bf16 split, CTA 128x128, 8 warps, warp tile 64x32, K-chunk 32.
// 2-stage cp.async pipeline. SPLIT=true: emit bf16 hi/lo split.
#define KC 32
#define TS 80
#define SM_A_HI 0
#define SM_A_LO 10240
#define SM_B_HI 20480
#define SM_B_LO 30720
#define GSTG 40960
#define GEMM_SMEM (2 * GSTG)

template <bool SPLIT>
__global__ __launch_bounds__(256, 2)
void gemm_mma_kernel(const __nv_bfloat16* __restrict__ Ahi,
                     const __nv_bfloat16* __restrict__ Alo,
                     const __nv_bfloat16* __restrict__ Whi,
                     const __nv_bfloat16* __restrict__ Wlo,
                     const float* __restrict__ bias,
                     float* __restrict__ C,
                     __nv_bfloat16* __restrict__ Chi,
                     __nv_bfloat16* __restrict__ Clo,
                     float alpha)
{
    extern __shared__ __align__(16) char smem[];
    int tid = threadIdx.x;
    int wid = tid >> 5;
    int lane = tid & 31;
    int m0 = blockIdx.y * 128;
    int n0 = blockIdx.x * 128;
    int wm = wid & 1;
    int wn = wid >> 1;

    float acc[4][4][4];
    #pragma unroll
    for (int mt = 0; mt < 4; ++mt)
        #pragma unroll
        for (int nt = 0; nt < 4; ++nt)
            #pragma unroll
            for (int k = 0; k < 4; ++k) acc[mt][nt][k] = 0.0f;

    uint32_t sb = smem_u32(smem);
    int lr = lane & 7;
    int qq = lane >> 3;
    uint32_t aHiA[4], aLoA[4], bHiA[2], bLoA[2];
    #pragma unroll
    for (int mt = 0; mt < 4; ++mt) {
        int row = wm * 64 + mt * 16 + lr + (qq & 1) * 8;
        uint32_t off = row * TS + (qq >> 1) * 16;
        aHiA[mt] = sb + SM_A_HI + off;
        aLoA[mt] = sb + SM_A_LO + off;
    }
    #pragma unroll
    for (int p = 0; p < 2; ++p) {
        int row = wn * 32 + p * 16 + lr + (qq & 1) * 8;
        uint32_t off = row * TS + (qq >> 1) * 16;
        bHiA[p] = sb + SM_B_HI + off;
        bLoA[p] = sb + SM_B_LO + off;
    }

    int glr = tid >> 2;
    int glj = tid & 3;

    auto prefetchG = [&](int c, uint32_t sbase) {
        int kc = c * KC;
        #pragma unroll
        for (int it = 0; it < 2; ++it) {
            int r = glr + it * 64;
            uint32_t so = sbase + r * TS + glj * 16;
            size_t ga = (size_t)(m0 + r) * EE + kc + glj * 8;
            size_t gb = (size_t)(n0 + r) * EE + kc + glj * 8;
            cpa16(sb + SM_A_HI + so, Ahi + ga);
            cpa16(sb + SM_A_LO + so, Alo + ga);
            cpa16(sb + SM_B_HI + so, Whi + gb);
            cpa16(sb + SM_B_LO + so, Wlo + gb);
        }
    };

    prefetchG(0, 0);
    CP_COMMIT();

    const int NITER = EE / KC;   // 32
    for (int c = 0; c < NITER; ++c) {
        uint32_t cs = (uint32_t)(c & 1) * GSTG;
        if (c + 1 < NITER) {
            prefetchG(c + 1, (uint32_t)((c + 1) & 1) * GSTG);
            CP_COMMIT();
            CP_WAIT(1);
        } else {
            CP_WAIT(0);
        }
        __syncthreads();

        #pragma unroll
        for (int ks = 0; ks < 2; ++ks) {
            uint32_t koB = cs + ks * 32;
            uint32_t aH[4][4], bH[2][4];
            #pragma unroll
            for (int mt = 0; mt < 4; ++mt) ldsm4(aH[mt], aHiA[mt] + koB);
            #pragma unroll
            for (int p = 0; p < 2; ++p) ldsm4(bH[p], bHiA[p] + koB);
            #pragma unroll
            for (int mt = 0; mt < 4; ++mt)
                #pragma unroll
                for (int nt = 0; nt < 4; ++nt)
                    mma16816(acc[mt][nt], aH[mt], bH[nt >> 1][nt & 1], bH[nt >> 1][(nt & 1) + 2]);
            {
                uint32_t bL[2][4];
                #pragma unroll
                for (int p = 0; p < 2; ++p) ldsm4(bL[p], bLoA[p] + koB);
                #pragma unroll
                for (int mt = 0; mt < 4; ++mt)
                    #pragma unroll
                    for (int nt = 0; nt < 4; ++nt)
                        mma16816(acc[mt][nt], aH[mt], bL[nt >> 1][nt & 1], bL[nt >> 1][(nt & 1) + 2]);
            }
            {
                uint32_t aL[4][4];
                #pragma unroll
                for (int mt = 0; mt < 4; ++mt) ldsm4(aL[mt], aLoA[mt] + koB);
                #pragma unroll
                for (int mt = 0; mt < 4; ++mt)
                    #pragma unroll
                    for (int nt = 0; nt < 4; ++nt)
                        mma16816(acc[mt][nt], aL[mt], bH[nt >> 1][nt & 1], bH[nt >> 1][(nt & 1) + 2]);
            }
        }
        __syncthreads();
    }

    int gid = lane >> 2;
    int tig = lane & 3;
    #pragma unroll
    for (int nt = 0; nt < 4; ++nt) {
        int col = n0 + wn * 32 + nt * 8 + tig * 2;
        float b0 = bias[col], b1 = bias[col + 1];
        #pragma unroll
        for (int mt = 0; mt < 4; ++mt) {
            int row = m0 + wm * 64 + mt * 16 + gid;
            float v0 = alpha * (acc[mt][nt][0] + b0);
            float v1 = alpha * (acc[mt][nt][1] + b1);
            float v2 = alpha * (acc[mt][nt][2] + b0);
            float v3 = alpha * (acc[mt][nt][3] + b1);
            if (SPLIT) {
                uint32_t h0 = pack_hi2(v0, v1);
                uint32_t l0 = pack_lo2(v0, v1, h0);
                uint32_t h1 = pack_hi2(v2, v3);
                uint32_t l1 = pack_lo2(v2, v3, h1);
                *(uint32_t*)&Chi[(size_t)row * EE + col] = h0;
                *(uint32_t*)&Clo[(size_t)row * EE + col] = l0;
                *(uint32_t*)&Chi[(size_t)(row + 8) * EE + col] = h1;
                *(uint32_t*)&Clo[(size_t)(row + 8) * EE + col] = l1;
            } else {
                float2 w0 = {v0, v1}, w1 = {v2, v3};
                *(float2*)&C[(size_t)row * EE + col] = w0;
                *(float2*)&C[(size_t)(row + 8) * EE + col] = w1;
            }
        }
    }
}

// ---------------- fused attention (flash, mma.sync bf16-split, cp.async pipe) --------
// CTA: 128 q rows, 8 warps. Key tile 64. 2-stage pipeline over K/V/bias/mask.
#define ATS 144
#define AK_HI 0
#define AK_LO 9216
#define AV_HI 18432
#define AV_LO 27648
#define A_BIAS 36864          // 128 rows x 272B (68 floats)
#define A_MSK  71680          // 64 floats
#define ASTG   71936
#define ATT_SMEM (2 * ASTG)   // 143872

__global__ __launch_bounds__(256)
void attention_mma_kernel(const float* __restrict__ attn_bias,
                          const float* __restrict__ attn_mask)
{
    extern __shared__ __align__(16) char dsm[];
    uint32_t sb = smem_u32(dsm);

    int tid = threadIdx.x;
    int wid = tid >> 5;
    int lane = tid & 31;
    int gid = lane >> 2;
    int tig = lane & 3;
    int lr = lane & 7;
    int qq = lane >> 3;
    int bh = blockIdx.y;
    int b = bh >> 4, h = bh & 15;
    int q0 = blockIdx.x * 128;
    int wq = wid * 16;

    // ---- stage Q tile (128x64 hi+lo) in stage-0 area, extract fragments ----
    #pragma unroll
    for (int i = 0; i < 4; ++i) {
        int v = tid + i * 256;
        int r = v >> 3;
        int j = v & 7;
        size_t ga = (size_t)(b * SS + q0 + r) * EE + h * DD + j * 8;
        *(uint4*)(dsm + r * ATS + j * 16) = *(const uint4*)(g_Qhi + ga);
        *(uint4*)(dsm + 18432 + r * ATS + j * 16) = *(const uint4*)(g_Qlo + ga);
    }
    __syncthreads();

    uint32_t aQh[4][4], aQl[4][4];
    {
        uint32_t base = (uint32_t)((wq + lr + (qq & 1) * 8) * ATS + (qq >> 1) * 16);
        #pragma unroll
        for (int kc = 0; kc < 4; ++kc) {
            ldsm4(aQh[kc], sb + base + kc * 32);
            ldsm4(aQl[kc], sb + 18432 + base + kc * 32);
        }
    }
    __syncthreads();   // Q reads done before stage-0 prefetch overwrites

    float o[8][4];
    #pragma unroll
    for (int nt = 0; nt < 8; ++nt)
        #pragma unroll
        for (int k = 0; k < 4; ++k) o[nt][k] = 0.0f;
    float m0r = -INFINITY, m1r = -INFINITY, l0r = 0.0f, l1r = 0.0f;

    int qr0 = q0 + wq + gid;
    const float* biasCTA = attn_bias + ((size_t)(b * HH + h) * SS + q0) * SS;
    const float* amRow0 = attn_mask + (size_t)qr0 * SS;
    const float* amRow1 = amRow0 + 8 * SS;

    uint32_t kfb = (uint32_t)((lr + (qq & 1) * 8) * ATS + (qq >> 1) * 16);
    int vkey = ((lane >> 3) & 1) * 8 + lr;
    int vd = (lane >> 4) * 8;

    auto prefetchA = [&](int nk0, uint32_t nbase) {
        uint32_t nb = sb + nbase;
        #pragma unroll
        for (int i = 0; i < 8; ++i) {
            int v = tid + i * 256;
            int arr = v >> 9;
            int rem = v & 511;
            int r = rem >> 3;
            int j = rem & 7;
            const __nv_bfloat16* src = (arr == 0) ? g_Khi : (arr == 1) ? g_Klo
                                     : (arr == 2) ? g_Vhi : g_Vlo;
            cpa16(nb + arr * 9216 + r * ATS + j * 16,
                  src + (size_t)(b * SS + nk0 + r) * EE + h * DD + j * 8);
        }
        #pragma unroll
        for (int i = 0; i < 8; ++i) {
            int v = tid + i * 256;
            int r = v >> 4;
            int c16 = v & 15;
            cpa16(nb + A_BIAS + r * 272 + c16 * 16,
                  biasCTA + (size_t)r * SS + nk0 + c16 * 4);
        }
        if (tid < 16)
            cpa16(nb + A_MSK + tid * 16, g_maskflag + b * SS + nk0 + tid * 4);
    };

    prefetchA(0, 0);
    CP_COMMIT();

    for (int t = 0; t < SS / 64; ++t) {
        int k0 = t * 64;
        uint32_t cs = (uint32_t)(t & 1) * ASTG;
        if (t + 1 < SS / 64) {
            prefetchA(k0 + 64, (uint32_t)((t + 1) & 1) * ASTG);
            CP_COMMIT();
            CP_WAIT(1);
        } else {
            CP_WAIT(0);
        }
        __syncthreads();

        const float* biasS = (const float*)(dsm + cs + A_BIAS);
        const float* maskS = (const float*)(dsm + cs + A_MSK);

        // ---- S = Q K^T (3-term split), 8-reg K live set ----
        float s[8][4];
        #pragma unroll
        for (int nt = 0; nt < 8; ++nt)
            #pragma unroll
            for (int k = 0; k < 4; ++k) s[nt][k] = 0.0f;

        #pragma unroll
        for (int kc = 0; kc < 4; ++kc) {
            uint32_t koB = cs + kfb + kc * 32;
            #pragma unroll
            for (int ng = 0; ng < 4; ++ng) {
                uint32_t bKh[4], bKl[4];
                ldsm4(bKh, sb + AK_HI + (uint32_t)(ng * 16 * ATS) + koB);
                ldsm4(bKl, sb + AK_LO + (uint32_t)(ng * 16 * ATS) + koB);
                int nt0 = 2 * ng, nt1 = 2 * ng + 1;
                mma16816(s[nt0], aQh[kc], bKh[0], bKh[2]);
                mma16816(s[nt1], aQh[kc], bKh[1], bKh[3]);
                mma16816(s[nt0], aQh[kc], bKl[0], bKl[2]);
                mma16816(s[nt1], aQh[kc], bKl[1], bKl[3]);
                mma16816(s[nt0], aQl[kc], bKh[0], bKh[2]);
                mma16816(s[nt1], aQl[kc], bKh[1], bKh[3]);
            }
        }

        // ---- bias (smem) + attn_mask (global/L2) + padding mask ----
        int brow0 = (wq + gid) * 68;
        int brow1 = brow0 + 8 * 68;
        #pragma unroll
        for (int nt = 0; nt < 8; ++nt) {
            int col = nt * 8 + tig * 2;
            float2 bb0 = *(const float2*)&biasS[brow0 + col];
            float2 bb1 = *(const float2*)&biasS[brow1 + col];
            float2 am0 = *(const float2*)&amRow0[k0 + col];
            float2 am1 = *(const float2*)&amRow1[k0 + col];
            float mf0 = maskS[col], mf1 = maskS[col + 1];
            s[nt][0] = (mf0 > 0.5f) ? NEG_INF : s[nt][0] + bb0.x + am0.x;
            s[nt][1] = (mf1 > 0.5f) ? NEG_INF : s[nt][1] + bb0.y + am0.y;
            s[nt][2] = (mf0 > 0.5f) ? NEG_INF : s[nt][2] + bb1.x + am1.x;
            s[nt][3] = (mf1 > 0.5f) ? NEG_INF : s[nt][3] + bb1.y + am1.y;
        }

        // ---- online softmax ----
        float mx0 = -INFINITY, mx1 = -INFINITY;
        #pragma unroll
        for (int nt = 0; nt < 8; ++nt) {
            mx0 = fmaxf(mx0, fmaxf(s[nt][0], s[nt][1]));
            mx1 = fmaxf(mx1, fmaxf(s[nt][2], s[nt][3]));
        }
        mx0 = fmaxf(mx0, __shfl_xor_sync(0xffffffffu, mx0, 1));
        mx0 = fmaxf(mx0, __shfl_xor_sync(0xffffffffu, mx0, 2));
        mx1 = fmaxf(mx1, __shfl_xor_sync(0xffffffffu, mx1, 1));
        mx1 = fmaxf(mx1, __shfl_xor_sync(0xffffffffu, mx1, 2));
        float mn0 = fmaxf(m0r, mx0), mn1 = fmaxf(m1r, mx1);
        float sc0 = __expf(m0r - mn0), sc1 = __expf(m1r - mn1);
        float rs0 = 0.0f, rs1 = 0.0f;
        #pragma unroll
        for (int nt = 0; nt < 8; ++nt) {
            s[nt][0] = __expf(s[nt][0] - mn0);
            s[nt][1] = __expf(s[nt][1] - mn0);
            s[nt][2] = __expf(s[nt][2] - mn1);
            s[nt][3] = __expf(s[nt][3] - mn1);
            rs0 += s[nt][0] + s[nt][1];
            rs1 += s[nt][2] + s[nt][3];
        }
        rs0 += __shfl_xor_sync(0xffffffffu, rs0, 1);
        rs0 += __shfl_xor_sync(0xffffffffu, rs0, 2);
        rs1 += __shfl_xor_sync(0xffffffffu, rs1, 1);
        rs1 += __shfl_xor_sync(0xffffffffu, rs1, 2);
        l0r = l0r * sc0 + rs0;
        l1r = l1r * sc1 + rs1;
        m0r = mn0; m1r = mn1;
        #pragma unroll
        for (int nt = 0; nt < 8; ++nt) {
            o[nt][0] *= sc0; o[nt][1] *= sc0;
            o[nt][2] *= sc1; o[nt][3] *= sc1;
        }

        // ---- pack P hi/lo as A-fragments ----
        uint32_t ph[4][4], pl[4][4];
        #pragma unroll
        for (int kc = 0; kc < 4; ++kc) {
            int n0t = 2 * kc, n1t = 2 * kc + 1;
            ph[kc][0] = pack_hi2(s[n0t][0], s[n0t][1]);
            pl[kc][0] = pack_lo2(s[n0t][0], s[n0t][1], ph[kc][0]);
            ph[kc][1] = pack_hi2(s[n0t][2], s[n0t][3]);
            pl[kc][1] = pack_lo2(s[n0t][2], s[n0t][3], ph[kc][1]);
            ph[kc][2] = pack_hi2(s[n1t][0], s[n1t][1]);
            pl[kc][2] = pack_lo2(s[n1t][0], s[n1t][1], ph[kc][2]);
            ph[kc][3] = pack_hi2(s[n1t][2], s[n1t][3]);
            pl[kc][3] = pack_lo2(s[n1t][2], s[n1t][3], ph[kc][3]);
        }

        // ---- O += P V (3-term split), 8-reg V live set ----
        #pragma unroll
        for (int kc = 0; kc < 4; ++kc) {
            #pragma unroll
            for (int dg = 0; dg < 4; ++dg) {
                uint32_t off = cs + (uint32_t)((kc * 16 + vkey) * ATS + (dg * 16 + vd) * 2);
                uint32_t vh[4], vl[4];
                ldsm4t(vh, sb + AV_HI + off);
                ldsm4t(vl, sb + AV_LO + off);
                int nt0 = 2 * dg, nt1 = 2 * dg + 1;
                mma16816(o[nt0], ph[kc], vh[0], vh[1]);
                mma16816(o[nt0], ph[kc], vl[0], vl[1]);
                mma16816(o[nt0], pl[kc], vh[0], vh[1]);
                mma16816(o[nt1], ph[kc], vh[2], vh[3]);
                mma16816(o[nt1], ph[kc], vl[2], vl[3]);
                mma16816(o[nt1], pl[kc], vh[2], vh[3]);
            }
        }
        __syncthreads();
    }

    // ---- normalize + emit bf16 hi/lo split ----
    float inv0 = 1.0f / l0r, inv1 = 1.0f / l1r;
    size_t row0 = (size_t)(b * SS + qr0) * EE + h * DD;
    size_t row1 = row0 + 8 * EE;
    #pragma unroll
    for (int nt = 0; nt < 8; ++nt) {
        int col = nt * 8 + tig * 2;
        float v0 = o[nt][0] * inv0, v1 = o[nt][1] * inv0;
        float v2 = o[nt][2] * inv1, v3 = o[nt][3] * inv1;
        uint32_t h0 = pack_hi2(v0, v1);
        uint32_t l0 = pack_lo2(v0, v1, h0);
        uint32_t h1 = pack_hi2(v2, v3);
        uint32_t l1 = pack_lo2(v2, v3, h1);
        *(uint32_t*)&g_AThi[row0 + col] = h0;
        *(uint32_t*)&g_ATlo[row0 + col] = l0;
        *(uint32_t*)&g_AThi[row1 + col] = h1;
        *(uint32_t*)&g_ATlo[row1 + col] = l1;
    }
}

// ---------------- launch ----------------
extern "C" void kernel_launch(void* const* d_in, const int* in_sizes, int n_in,
                              void* d_out, int out_size) {
    const float* query     = (const float*)d_in[0];
    const float* attn_bias = (const float*)d_in[3];
    const void*  kpm       = d_in[4];
    const float* attn_mask = (const float*)d_in[5];
    const float* Wq = (const float*)d_in[9];
    const float* bq = (const float*)d_in[10];
    const float* Wk = (const float*)d_in[11];
    const float* bk = (const float*)d_in[12];
    const float* Wv = (const float*)d_in[13];
    const float* bv = (const float*)d_in[14];
    const float* Wo = (const float*)d_in[15];
    const float* bo = (const float*)d_in[16];
    float* out = (float*)d_out;

    __nv_bfloat16 *gXhi, *gXlo, *gQhi, *gQlo, *gKhi, *gKlo, *gVhi, *gVlo,
                  *gAThi, *gATlo, *gWhi, *gWlo;
    cudaGetSymbolAddress((void**)&gXhi, g_Xhi);
    cudaGetSymbolAddress((void**)&gXlo, g_Xlo);
    cudaGetSymbolAddress((void**)&gQhi, g_Qhi);
    cudaGetSymbolAddress((void**)&gQlo, g_Qlo);
    cudaGetSymbolAddress((void**)&gKhi, g_Khi);
    cudaGetSymbolAddress((void**)&gKlo, g_Klo);
    cudaGetSymbolAddress((void**)&gVhi, g_Vhi);
    cudaGetSymbolAddress((void**)&gVlo, g_Vlo);
    cudaGetSymbolAddress((void**)&gAThi, g_AThi);
    cudaGetSymbolAddress((void**)&gATlo, g_ATlo);
    cudaGetSymbolAddress((void**)&gWhi, g_Whi);
    cudaGetSymbolAddress((void**)&gWlo, g_Wlo);

    cudaFuncSetAttribute(gemm_mma_kernel<true>,
                         cudaFuncAttributeMaxDynamicSharedMemorySize, GEMM_SMEM);
    cudaFuncSetAttribute(gemm_mma_kernel<false>,
                         cudaFuncAttributeMaxDynamicSharedMemorySize, GEMM_SMEM);
    cudaFuncSetAttribute(attention_mma_kernel,
                         cudaFuncAttributeMaxDynamicSharedMemorySize, ATT_SMEM);

    const int nq4 = BB * SS * EE / 4;
    const int nw4 = EE * EE / 4;
    split_kernel<<<(nq4 + 255) / 256, 256>>>(query, gXhi, gXlo, nq4);
    split_kernel<<<(nw4 + 255) / 256, 256>>>(Wq, gWhi + 0 * (size_t)EE * EE, gWlo + 0 * (size_t)EE * EE, nw4);
    split_kernel<<<(nw4 + 255) / 256, 256>>>(Wk, gWhi + 1 * (size_t)EE * EE, gWlo + 1 * (size_t)EE * EE, nw4);
    split_kernel<<<(nw4 + 255) / 256, 256>>>(Wv, gWhi + 2 * (size_t)EE * EE, gWlo + 2 * (size_t)EE * EE, nw4);
    split_kernel<<<(nw4 + 255) / 256, 256>>>(Wo, gWhi + 3 * (size_t)EE * EE, gWlo + 3 * (size_t)EE * EE, nw4);

    detect_mask_kernel<<<1, 256>>>(kpm);
    expand_mask_kernel<<<(BB * SS + 255) / 256, 256>>>(kpm);

    dim3 ggrid(EE / 128, BB * SS / 128);   // (8, 64)
    const float scaling = 0.125f;          // D^-0.5

    gemm_mma_kernel<true><<<ggrid, 256, GEMM_SMEM>>>(gXhi, gXlo,
        gWhi + 0 * (size_t)EE * EE, gWlo + 0 * (size_t)EE * EE, bq,
        nullptr, gQhi, gQlo, scaling);
    gemm_mma_kernel<true><<<ggrid, 256, GEMM_SMEM>>>(gXhi, gXlo,
        gWhi + 1 * (size_t)EE * EE, gWlo + 1 * (size_t)EE * EE, bk,
        nullptr, gKhi, gKlo, 1.0f);
    gemm_mma_kernel<true><<<ggrid, 256, GEMM_SMEM>>>(gXhi, gXlo,
        gWhi + 2 * (size_t)EE * EE, gWlo + 2 * (size_t)EE * EE, bv,
        nullptr, gVhi, gVlo, 1.0f);

    attention_mma_kernel<<<dim3(SS / 128, BB * HH), 256, ATT_SMEM>>>(attn_bias, attn_mask);

    gemm_mma_kernel<false><<<ggrid, 256, GEMM_SMEM>>>(gAThi, gATlo,
        gWhi + 3 * (size_t)EE * EE, gWlo + 3 * (size_t)EE * EE, bo,
        out, nullptr, nullptr, 1.0f);
}

// round 13
// speedup vs baseline: 1.3403x; 1.3403x over previous
#include <cuda_runtime.h>
#include <cuda_bf16.h>
#include <cstdint>
#include <cstddef>

#define BB 8
#define SS 1024
#define EE 1024
#define HH 16
#define DD 64
#define NEG_INF (-3.402823466e38f)

// ---------------- scratch (no allocations allowed) ----------------
__device__ __nv_bfloat16 g_Xhi[BB * SS * EE];   // query split
__device__ __nv_bfloat16 g_Xlo[BB * SS * EE];
__device__ __nv_bfloat16 g_Qhi[BB * SS * EE];   // projected q/k/v splits
__device__ __nv_bfloat16 g_Qlo[BB * SS * EE];
__device__ __nv_bfloat16 g_Khi[BB * SS * EE];
__device__ __nv_bfloat16 g_Klo[BB * SS * EE];
__device__ __nv_bfloat16 g_Vhi[BB * SS * EE];
__device__ __nv_bfloat16 g_Vlo[BB * SS * EE];
__device__ __nv_bfloat16 g_AThi[BB * SS * EE];  // attention output split
__device__ __nv_bfloat16 g_ATlo[BB * SS * EE];
__device__ __nv_bfloat16 g_Whi[4][EE * EE];     // Wq,Wk,Wv,Wo splits
__device__ __nv_bfloat16 g_Wlo[4][EE * EE];
__device__ float g_maskflag[BB * SS];
__device__ int   g_mask_dtype;

// ---------------- helpers ----------------
__device__ __forceinline__ uint32_t smem_u32(const void* p) {
    uint32_t a;
    asm("{ .reg .u64 t; cvta.to.shared.u64 t, %1; cvt.u32.u64 %0, t; }" : "=r"(a) : "l"(p));
    return a;
}
__device__ __forceinline__ void ldsm4(uint32_t* r, uint32_t addr) {
    asm volatile("ldmatrix.sync.aligned.m8n8.x4.shared.b16 {%0,%1,%2,%3}, [%4];"
        : "=r"(r[0]), "=r"(r[1]), "=r"(r[2]), "=r"(r[3]) : "r"(addr));
}
__device__ __forceinline__ void ldsm4t(uint32_t* r, uint32_t addr) {
    asm volatile("ldmatrix.sync.aligned.m8n8.x4.trans.shared.b16 {%0,%1,%2,%3}, [%4];"
        : "=r"(r[0]), "=r"(r[1]), "=r"(r[2]), "=r"(r[3]) : "r"(addr));
}
__device__ __forceinline__ void mma16816(float* c, const uint32_t* a, uint32_t b0, uint32_t b1) {
    asm volatile(
        "mma.sync.aligned.m16n8k16.row.col.f32.bf16.bf16.f32 "
        "{%0,%1,%2,%3}, {%4,%5,%6,%7}, {%8,%9}, {%0,%1,%2,%3};"
        : "+f"(c[0]), "+f"(c[1]), "+f"(c[2]), "+f"(c[3])
        : "r"(a[0]), "r"(a[1]), "r"(a[2]), "r"(a[3]), "r"(b0), "r"(b1));
}
__device__ __forceinline__ void cpa16(uint32_t saddr, const void* g) {
    asm volatile("cp.async.cg.shared.global [%0], [%1], 16;" :: "r"(saddr), "l"(g));
}
#define CP_COMMIT() asm volatile("cp.async.commit_group;" ::: "memory")
#define CP_WAIT(n)  asm volatile("cp.async.wait_group %0;" :: "n"(n) : "memory")

__device__ __forceinline__ uint32_t pack_hi2(float x, float y) {
    __nv_bfloat162 v = __halves2bfloat162(__float2bfloat16(x), __float2bfloat16(y));
    return *(uint32_t*)&v;
}
__device__ __forceinline__ uint32_t pack_lo2(float x, float y, uint32_t hi) {
    __nv_bfloat162 h = *(__nv_bfloat162*)&hi;
    __nv_bfloat162 v = __halves2bfloat162(
        __float2bfloat16(x - __bfloat162float(h.x)),
        __float2bfloat16(y - __bfloat162float(h.y)));
    return *(uint32_t*)&v;
}

// ---------------- fp32 -> bf16 hi/lo split ----------------
__global__ void split_kernel(const float* __restrict__ src,
                             __nv_bfloat16* __restrict__ hi,
                             __nv_bfloat16* __restrict__ lo, int n4) {
    int i = blockIdx.x * blockDim.x + threadIdx.x;
    if (i >= n4) return;
    float4 v = ((const float4*)src)[i];
    float vv[4] = {v.x, v.y, v.z, v.w};
    __nv_bfloat16 h[4], l[4];
    #pragma unroll
    for (int j = 0; j < 4; ++j) {
        h[j] = __float2bfloat16(vv[j]);
        l[j] = __float2bfloat16(vv[j] - __bfloat162float(h[j]));
    }
    __nv_bfloat162* ph = (__nv_bfloat162*)&hi[(size_t)i * 4];
    __nv_bfloat162* pl = (__nv_bfloat162*)&lo[(size_t)i * 4];
    ph[0] = __halves2bfloat162(h[0], h[1]);
    ph[1] = __halves2bfloat162(h[2], h[3]);
    pl[0] = __halves2bfloat162(l[0], l[1]);
    pl[1] = __halves2bfloat162(l[2], l[3]);
}

// ---------------- key_padding_mask dtype detection ----------------
__global__ void detect_mask_kernel(const void* mask) {
    const unsigned int* w = (const unsigned int*)mask;
    __shared__ int s_f32, s_big;
    if (threadIdx.x == 0) { s_f32 = 0; s_big = 0; }
    __syncthreads();
    int lf = 0, lb = 0;
    for (int i = threadIdx.x; i < 2048; i += blockDim.x) {
        unsigned int v = w[i];
        if (v == 0x3F800000u) lf = 1;
        else if (v > 1u) lb = 1;
    }
    if (lf) atomicOr(&s_f32, 1);
    if (lb) atomicOr(&s_big, 1);
    __syncthreads();
    if (threadIdx.x == 0)
        g_mask_dtype = s_f32 ? 2 : (s_big ? 0 : 1);
}

__global__ void expand_mask_kernel(const void* mask) {
    int i = blockIdx.x * blockDim.x + threadIdx.x;
    if (i >= BB * SS) return;
    int dt = g_mask_dtype;
    bool f;
    if (dt == 0)      f = ((const unsigned char*)mask)[i] != 0;
    else if (dt == 1) f = ((const int*)mask)[i] != 0;
    else              f = ((const float*)mask)[i] != 0.0f;
    g_maskflag[i] = f ? 1.0f : 0.0f;
}

// ---------------- mma.sync GEMM: C = alpha*(A@W^T + bias) ----------------
// 3-term bf16 split product, CTA 128x128, 8 warps, warp tile 64x32, K-chunk 32.
// Single-stage smem (R8 baseline). SPLIT=true: emit bf16 hi/lo split.
#define KC 32
#define TS 80
#define SM_A_HI 0
#define SM_A_LO 10240
#define SM_B_HI 20480
#define SM_B_LO 30720

template <bool SPLIT>
__global__ __launch_bounds__(256, 2)
void gemm_mma_kernel(const __nv_bfloat16* __restrict__ Ahi,
                     const __nv_bfloat16* __restrict__ Alo,
                     const __nv_bfloat16* __restrict__ Whi,
                     const __nv_bfloat16* __restrict__ Wlo,
                     const float* __restrict__ bias,
                     float* __restrict__ C,
                     __nv_bfloat16* __restrict__ Chi,
                     __nv_bfloat16* __restrict__ Clo,
                     float alpha)
{
    __shared__ __align__(16) char smem[40960];
    int tid = threadIdx.x;
    int wid = tid >> 5;
    int lane = tid & 31;
    int m0 = blockIdx.y * 128;
    int n0 = blockIdx.x * 128;
    int wm = wid & 1;
    int wn = wid >> 1;

    float acc[4][4][4];
    #pragma unroll
    for (int mt = 0; mt < 4; ++mt)
        #pragma unroll
        for (int nt = 0; nt < 4; ++nt)
            #pragma unroll
            for (int k = 0; k < 4; ++k) acc[mt][nt][k] = 0.0f;

    uint32_t sb = smem_u32(smem);
    int lr = lane & 7;
    int qq = lane >> 3;
    uint32_t aHiA[4], aLoA[4], bHiA[2], bLoA[2];
    #pragma unroll
    for (int mt = 0; mt < 4; ++mt) {
        int row = wm * 64 + mt * 16 + lr + (qq & 1) * 8;
        uint32_t off = row * TS + (qq >> 1) * 16;
        aHiA[mt] = sb + SM_A_HI + off;
        aLoA[mt] = sb + SM_A_LO + off;
    }
    #pragma unroll
    for (int p = 0; p < 2; ++p) {
        int row = wn * 32 + p * 16 + lr + (qq & 1) * 8;
        uint32_t off = row * TS + (qq >> 1) * 16;
        bHiA[p] = sb + SM_B_HI + off;
        bLoA[p] = sb + SM_B_LO + off;
    }

    int glr = tid >> 2;
    int glj = tid & 3;

    for (int c = 0; c < EE / KC; ++c) {
        int kc = c * KC;
        #pragma unroll
        for (int it = 0; it < 2; ++it) {
            int r = glr + it * 64;
            uint32_t so = r * TS + glj * 16;
            size_t ga = (size_t)(m0 + r) * EE + kc + glj * 8;
            size_t gb = (size_t)(n0 + r) * EE + kc + glj * 8;
            *(uint4*)(smem + SM_A_HI + so) = *(const uint4*)(Ahi + ga);
            *(uint4*)(smem + SM_A_LO + so) = *(const uint4*)(Alo + ga);
            *(uint4*)(smem + SM_B_HI + so) = *(const uint4*)(Whi + gb);
            *(uint4*)(smem + SM_B_LO + so) = *(const uint4*)(Wlo + gb);
        }
        __syncthreads();

        #pragma unroll
        for (int ks = 0; ks < 2; ++ks) {
            uint32_t koB = ks * 32;
            uint32_t aH[4][4], bH[2][4];
            #pragma unroll
            for (int mt = 0; mt < 4; ++mt) ldsm4(aH[mt], aHiA[mt] + koB);
            #pragma unroll
            for (int p = 0; p < 2; ++p) ldsm4(bH[p], bHiA[p] + koB);
            #pragma unroll
            for (int mt = 0; mt < 4; ++mt)
                #pragma unroll
                for (int nt = 0; nt < 4; ++nt)
                    mma16816(acc[mt][nt], aH[mt], bH[nt >> 1][nt & 1], bH[nt >> 1][(nt & 1) + 2]);
            {
                uint32_t bL[2][4];
                #pragma unroll
                for (int p = 0; p < 2; ++p) ldsm4(bL[p], bLoA[p] + koB);
                #pragma unroll
                for (int mt = 0; mt < 4; ++mt)
                    #pragma unroll
                    for (int nt = 0; nt < 4; ++nt)
                        mma16816(acc[mt][nt], aH[mt], bL[nt >> 1][nt & 1], bL[nt >> 1][(nt & 1) + 2]);
            }
            {
                uint32_t aL[4][4];
                #pragma unroll
                for (int mt = 0; mt < 4; ++mt) ldsm4(aL[mt], aLoA[mt] + koB);
                #pragma unroll
                for (int mt = 0; mt < 4; ++mt)
                    #pragma unroll
                    for (int nt = 0; nt < 4; ++nt)
                        mma16816(acc[mt][nt], aL[mt], bH[nt >> 1][nt & 1], bH[nt >> 1][(nt & 1) + 2]);
            }
        }
        __syncthreads();
    }

    int gid = lane >> 2;
    int tig = lane & 3;
    #pragma unroll
    for (int nt = 0; nt < 4; ++nt) {
        int col = n0 + wn * 32 + nt * 8 + tig * 2;
        float b0 = bias[col], b1 = bias[col + 1];
        #pragma unroll
        for (int mt = 0; mt < 4; ++mt) {
            int row = m0 + wm * 64 + mt * 16 + gid;
            float v0 = alpha * (acc[mt][nt][0] + b0);
            float v1 = alpha * (acc[mt][nt][1] + b1);
            float v2 = alpha * (acc[mt][nt][2] + b0);
            float v3 = alpha * (acc[mt][nt][3] + b1);
            if (SPLIT) {
                uint32_t h0 = pack_hi2(v0, v1);
                uint32_t l0 = pack_lo2(v0, v1, h0);
                uint32_t h1 = pack_hi2(v2, v3);
                uint32_t l1 = pack_lo2(v2, v3, h1);
                *(uint32_t*)&Chi[(size_t)row * EE + col] = h0;
                *(uint32_t*)&Clo[(size_t)row * EE + col] = l0;
                *(uint32_t*)&Chi[(size_t)(row + 8) * EE + col] = h1;
                *(uint32_t*)&Clo[(size_t)(row + 8) * EE + col] = l1;
            } else {
                float2 w0 = {v0, v1}, w1 = {v2, v3};
                *(float2*)&C[(size_t)row * EE + col] = w0;
                *(float2*)&C[(size_t)(row + 8) * EE + col] = w1;
            }
        }
    }
}

// ---------------- fused attention (flash, mma.sync bf16-split) ----------------
// CTA: 128 q rows, 8 warps. Key tile 64. K/V (+mask) double-buffered via
// cp.async; attn_bias + attn_mask remain direct LDGs (R8 style).
#define ATS 144
#define AK_HI 0
#define AK_LO 9216
#define AV_HI 18432
#define AV_LO 27648
#define A_MSK 36864          // 64 floats = 256 B
#define ASTG  37120
#define ATT_SMEM (2 * ASTG)  // 74240

__global__ __launch_bounds__(256)
void attention_mma_kernel(const float* __restrict__ attn_bias,
                          const float* __restrict__ attn_mask)
{
    extern __shared__ __align__(16) char dsm[];
    uint32_t sb = smem_u32(dsm);

    int tid = threadIdx.x;
    int wid = tid >> 5;
    int lane = tid & 31;
    int gid = lane >> 2;
    int tig = lane & 3;
    int lr = lane & 7;
    int qq = lane >> 3;
    int bh = blockIdx.y;
    int b = bh >> 4, h = bh & 15;
    int q0 = blockIdx.x * 128;
    int wq = wid * 16;

    // ---- stage Q tile (128x64 hi+lo) in stage-0 area, extract fragments ----
    #pragma unroll
    for (int i = 0; i < 4; ++i) {
        int v = tid + i * 256;
        int r = v >> 3;
        int j = v & 7;
        size_t ga = (size_t)(b * SS + q0 + r) * EE + h * DD + j * 8;
        *(uint4*)(dsm + r * ATS + j * 16) = *(const uint4*)(g_Qhi + ga);
        *(uint4*)(dsm + 18432 + r * ATS + j * 16) = *(const uint4*)(g_Qlo + ga);
    }
    __syncthreads();

    uint32_t aQh[4][4], aQl[4][4];
    {
        uint32_t base = (uint32_t)((wq + lr + (qq & 1) * 8) * ATS + (qq >> 1) * 16);
        #pragma unroll
        for (int kc = 0; kc < 4; ++kc) {
            ldsm4(aQh[kc], sb + base + kc * 32);
            ldsm4(aQl[kc], sb + 18432 + base + kc * 32);
        }
    }
    __syncthreads();   // Q reads done before stage-0 prefetch overwrites

    float o[8][4];
    #pragma unroll
    for (int nt = 0; nt < 8; ++nt)
        #pragma unroll
        for (int k = 0; k < 4; ++k) o[nt][k] = 0.0f;
    float m0r = -INFINITY, m1r = -INFINITY, l0r = 0.0f, l1r = 0.0f;

    int qr0 = q0 + wq + gid;
    const float* biasRow0 = attn_bias + ((size_t)(b * HH + h) * SS + qr0) * SS;
    const float* biasRow1 = biasRow0 + 8 * SS;
    const float* amRow0 = attn_mask + (size_t)qr0 * SS;
    const float* amRow1 = amRow0 + 8 * SS;

    uint32_t kfb = (uint32_t)((lr + (qq & 1) * 8) * ATS + (qq >> 1) * 16);
    int vkey = ((lane >> 3) & 1) * 8 + lr;
    int vd = (lane >> 4) * 8;

    auto prefetchA = [&](int nk0, uint32_t nbase) {
        uint32_t nb = sb + nbase;
        #pragma unroll
        for (int i = 0; i < 8; ++i) {
            int v = tid + i * 256;
            int arr = v >> 9;
            int rem = v & 511;
            int r = rem >> 3;
            int j = rem & 7;
            const __nv_bfloat16* src = (arr == 0) ? g_Khi : (arr == 1) ? g_Klo
                                     : (arr == 2) ? g_Vhi : g_Vlo;
            cpa16(nb + arr * 9216 + r * ATS + j * 16,
                  src + (size_t)(b * SS + nk0 + r) * EE + h * DD + j * 8);
        }
        if (tid < 16)
            cpa16(nb + A_MSK + tid * 16, g_maskflag + b * SS + nk0 + tid * 4);
    };

    prefetchA(0, 0);
    CP_COMMIT();

    for (int t = 0; t < SS / 64; ++t) {
        int k0 = t * 64;
        uint32_t cs = (uint32_t)(t & 1) * ASTG;
        if (t + 1 < SS / 64) {
            prefetchA(k0 + 64, (uint32_t)((t + 1) & 1) * ASTG);
            CP_COMMIT();
            CP_WAIT(1);
        } else {
            CP_WAIT(0);
        }
        __syncthreads();

        const float* maskS = (const float*)(dsm + cs + A_MSK);

        // ---- S = Q K^T (3-term split), 8-reg K live set ----
        float s[8][4];
        #pragma unroll
        for (int nt = 0; nt < 8; ++nt)
            #pragma unroll
            for (int k = 0; k < 4; ++k) s[nt][k] = 0.0f;

        #pragma unroll
        for (int kc = 0; kc < 4; ++kc) {
            uint32_t koB = cs + kfb + kc * 32;
            #pragma unroll
            for (int ng = 0; ng < 4; ++ng) {
                uint32_t bKh[4], bKl[4];
                ldsm4(bKh, sb + AK_HI + (uint32_t)(ng * 16 * ATS) + koB);
                ldsm4(bKl, sb + AK_LO + (uint32_t)(ng * 16 * ATS) + koB);
                int nt0 = 2 * ng, nt1 = 2 * ng + 1;
                mma16816(s[nt0], aQh[kc], bKh[0], bKh[2]);
                mma16816(s[nt1], aQh[kc], bKh[1], bKh[3]);
                mma16816(s[nt0], aQh[kc], bKl[0], bKl[2]);
                mma16816(s[nt1], aQh[kc], bKl[1], bKl[3]);
                mma16816(s[nt0], aQl[kc], bKh[0], bKh[2]);
                mma16816(s[nt1], aQl[kc], bKh[1], bKh[3]);
            }
        }

        // ---- bias + attn_mask (direct LDG) + padding mask (smem) ----
        #pragma unroll
        for (int nt = 0; nt < 8; ++nt) {
            int col = nt * 8 + tig * 2;
            float2 bb0 = *(const float2*)&biasRow0[k0 + col];
            float2 bb1 = *(const float2*)&biasRow1[k0 + col];
            float2 am0 = *(const float2*)&amRow0[k0 + col];
            float2 am1 = *(const float2*)&amRow1[k0 + col];
            float mf0 = maskS[col], mf1 = maskS[col + 1];
            s[nt][0] = (mf0 > 0.5f) ? NEG_INF : s[nt][0] + bb0.x + am0.x;
            s[nt][1] = (mf1 > 0.5f) ? NEG_INF : s[nt][1] + bb0.y + am0.y;
            s[nt][2] = (mf0 > 0.5f) ? NEG_INF : s[nt][2] + bb1.x + am1.x;
            s[nt][3] = (mf1 > 0.5f) ? NEG_INF : s[nt][3] + bb1.y + am1.y;
        }

        // ---- online softmax (rows gid and gid+8) ----
        float mx0 = -INFINITY, mx1 = -INFINITY;
        #pragma unroll
        for (int nt = 0; nt < 8; ++nt) {
            mx0 = fmaxf(mx0, fmaxf(s[nt][0], s[nt][1]));
            mx1 = fmaxf(mx1, fmaxf(s[nt][2], s[nt][3]));
        }
        mx0 = fmaxf(mx0, __shfl_xor_sync(0xffffffffu, mx0, 1));
        mx0 = fmaxf(mx0, __shfl_xor_sync(0xffffffffu, mx0, 2));
        mx1 = fmaxf(mx1, __shfl_xor_sync(0xffffffffu, mx1, 1));
        mx1 = fmaxf(mx1, __shfl_xor_sync(0xffffffffu, mx1, 2));
        float mn0 = fmaxf(m0r, mx0), mn1 = fmaxf(m1r, mx1);
        float sc0 = __expf(m0r - mn0), sc1 = __expf(m1r - mn1);
        float rs0 = 0.0f, rs1 = 0.0f;
        #pragma unroll
        for (int nt = 0; nt < 8; ++nt) {
            s[nt][0] = __expf(s[nt][0] - mn0);
            s[nt][1] = __expf(s[nt][1] - mn0);
            s[nt][2] = __expf(s[nt][2] - mn1);
            s[nt][3] = __expf(s[nt][3] - mn1);
            rs0 += s[nt][0] + s[nt][1];
            rs1 += s[nt][2] + s[nt][3];
        }
        rs0 += __shfl_xor_sync(0xffffffffu, rs0, 1);
        rs0 += __shfl_xor_sync(0xffffffffu, rs0, 2);
        rs1 += __shfl_xor_sync(0xffffffffu, rs1, 1);
        rs1 += __shfl_xor_sync(0xffffffffu, rs1, 2);
        l0r = l0r * sc0 + rs0;
        l1r = l1r * sc1 + rs1;
        m0r = mn0; m1r = mn1;
        #pragma unroll
        for (int nt = 0; nt < 8; ++nt) {
            o[nt][0] *= sc0; o[nt][1] *= sc0;
            o[nt][2] *= sc1; o[nt][3] *= sc1;
        }

        // ---- pack P hi/lo as A-fragments ----
        uint32_t ph[4][4], pl[4][4];
        #pragma unroll
        for (int kc = 0; kc < 4; ++kc) {
            int n0t = 2 * kc, n1t = 2 * kc + 1;
            ph[kc][0] = pack_hi2(s[n0t][0], s[n0t][1]);
            pl[kc][0] = pack_lo2(s[n0t][0], s[n0t][1], ph[kc][0]);
            ph[kc][1] = pack_hi2(s[n0t][2], s[n0t][3]);
            pl[kc][1] = pack_lo2(s[n0t][2], s[n0t][3], ph[kc][1]);
            ph[kc][2] = pack_hi2(s[n1t][0], s[n1t][1]);
            pl[kc][2] = pack_lo2(s[n1t][0], s[n1t][1], ph[kc][2]);
            ph[kc][3] = pack_hi2(s[n1t][2], s[n1t][3]);
            pl[kc][3] = pack_lo2(s[n1t][2], s[n1t][3], ph[kc][3]);
        }

        // ---- O += P V (3-term split), 8-reg V live set ----
        #pragma unroll
        for (int kc = 0; kc < 4; ++kc) {
            #pragma unroll
            for (int dg = 0; dg < 4; ++dg) {
                uint32_t off = cs + (uint32_t)((kc * 16 + vkey) * ATS + (dg * 16 + vd) * 2);
                uint32_t vh[4], vl[4];
                ldsm4t(vh, sb + AV_HI + off);
                ldsm4t(vl, sb + AV_LO + off);
                int nt0 = 2 * dg, nt1 = 2 * dg + 1;
                mma16816(o[nt0], ph[kc], vh[0], vh[1]);
                mma16816(o[nt0], ph[kc], vl[0], vl[1]);
                mma16816(o[nt0], pl[kc], vh[0], vh[1]);
                mma16816(o[nt1], ph[kc], vh[2], vh[3]);
                mma16816(o[nt1], ph[kc], vl[2], vl[3]);
                mma16816(o[nt1], pl[kc], vh[2], vh[3]);
            }
        }
        __syncthreads();
    }

    // ---- normalize + emit bf16 hi/lo split ----
    float inv0 = 1.0f / l0r, inv1 = 1.0f / l1r;
    size_t row0 = (size_t)(b * SS + qr0) * EE + h * DD;
    size_t row1 = row0 + 8 * EE;
    #pragma unroll
    for (int nt = 0; nt < 8; ++nt) {
        int col = nt * 8 + tig * 2;
        float v0 = o[nt][0] * inv0, v1 = o[nt][1] * inv0;
        float v2 = o[nt][2] * inv1, v3 = o[nt][3] * inv1;
        uint32_t h0 = pack_hi2(v0, v1);
        uint32_t l0 = pack_lo2(v0, v1, h0);
        uint32_t h1 = pack_hi2(v2, v3);
        uint32_t l1 = pack_lo2(v2, v3, h1);
        *(uint32_t*)&g_AThi[row0 + col] = h0;
        *(uint32_t*)&g_ATlo[row0 + col] = l0;
        *(uint32_t*)&g_AThi[row1 + col] = h1;
        *(uint32_t*)&g_ATlo[row1 + col] = l1;
    }
}

// ---------------- launch ----------------
extern "C" void kernel_launch(void* const* d_in, const int* in_sizes, int n_in,
                              void* d_out, int out_size) {
    const float* query     = (const float*)d_in[0];
    const float* attn_bias = (const float*)d_in[3];
    const void*  kpm       = d_in[4];
    const float* attn_mask = (const float*)d_in[5];
    const float* Wq = (const float*)d_in[9];
    const float* bq = (const float*)d_in[10];
    const float* Wk = (const float*)d_in[11];
    const float* bk = (const float*)d_in[12];
    const float* Wv = (const float*)d_in[13];
    const float* bv = (const float*)d_in[14];
    const float* Wo = (const float*)d_in[15];
    const float* bo = (const float*)d_in[16];
    float* out = (float*)d_out;

    __nv_bfloat16 *gXhi, *gXlo, *gQhi, *gQlo, *gKhi, *gKlo, *gVhi, *gVlo,
                  *gAThi, *gATlo, *gWhi, *gWlo;
    cudaGetSymbolAddress((void**)&gXhi, g_Xhi);
    cudaGetSymbolAddress((void**)&gXlo, g_Xlo);
    cudaGetSymbolAddress((void**)&gQhi, g_Qhi);
    cudaGetSymbolAddress((void**)&gQlo, g_Qlo);
    cudaGetSymbolAddress((void**)&gKhi, g_Khi);
    cudaGetSymbolAddress((void**)&gKlo, g_Klo);
    cudaGetSymbolAddress((void**)&gVhi, g_Vhi);
    cudaGetSymbolAddress((void**)&gVlo, g_Vlo);
    cudaGetSymbolAddress((void**)&gAThi, g_AThi);
    cudaGetSymbolAddress((void**)&gATlo, g_ATlo);
    cudaGetSymbolAddress((void**)&gWhi, g_Whi);
    cudaGetSymbolAddress((void**)&gWlo, g_Wlo);

    cudaFuncSetAttribute(attention_mma_kernel,
                         cudaFuncAttributeMaxDynamicSharedMemorySize, ATT_SMEM);

    const int nq4 = BB * SS * EE / 4;
    const int nw4 = EE * EE / 4;
    split_kernel<<<(nq4 + 255) / 256, 256>>>(query, gXhi, gXlo, nq4);
    split_kernel<<<(nw4 + 255) / 256, 256>>>(Wq, gWhi + 0 * (size_t)EE * EE, gWlo + 0 * (size_t)EE * EE, nw4);
    split_kernel<<<(nw4 + 255) / 256, 256>>>(Wk, gWhi + 1 * (size_t)EE * EE, gWlo + 1 * (size_t)EE * EE, nw4);
    split_kernel<<<(nw4 + 255) / 256, 256>>>(Wv, gWhi + 2 * (size_t)EE * EE, gWlo + 2 * (size_t)EE * EE, nw4);
    split_kernel<<<(nw4 + 255) / 256, 256>>>(Wo, gWhi + 3 * (size_t)EE * EE, gWlo + 3 * (size_t)EE * EE, nw4);

    detect_mask_kernel<<<1, 256>>>(kpm);
    expand_mask_kernel<<<(BB * SS + 255) / 256, 256>>>(kpm);

    dim3 ggrid(EE / 128, BB * SS / 128);   // (8, 64)
    const float scaling = 0.125f;          // D^-0.5

    gemm_mma_kernel<true><<<ggrid, 256>>>(gXhi, gXlo,
        gWhi + 0 * (size_t)EE * EE, gWlo + 0 * (size_t)EE * EE, bq,
        nullptr, gQhi, gQlo, scaling);
    gemm_mma_kernel<true><<<ggrid, 256>>>(gXhi, gXlo,
        gWhi + 1 * (size_t)EE * EE, gWlo + 1 * (size_t)EE * EE, bk,
        nullptr, gKhi, gKlo, 1.0f);
    gemm_mma_kernel<true><<<ggrid, 256>>>(gXhi, gXlo,
        gWhi + 2 * (size_t)EE * EE, gWlo + 2 * (size_t)EE * EE, bv,
        nullptr, gVhi, gVlo, 1.0f);

    attention_mma_kernel<<<dim3(SS / 128, BB * HH), 256, ATT_SMEM>>>(attn_bias, attn_mask);

    gemm_mma_kernel<false><<<ggrid, 256>>>(gAThi, gATlo,
        gWhi + 3 * (size_t)EE * EE, gWlo + 3 * (size_t)EE * EE, bo,
        out, nullptr, nullptr, 1.0f);
}

// round 14
// speedup vs baseline: 1.3953x; 1.0410x over previous
#include <cuda_runtime.h>
#include <cuda_bf16.h>
#include <cstdint>
#include <cstddef>

#define BB 8
#define SS 1024
#define EE 1024
#define HH 16
#define DD 64
#define NEG_INF (-3.402823466e38f)

// ---------------- scratch (no allocations allowed) ----------------
__device__ __nv_bfloat16 g_Xhi[BB * SS * EE];   // query split
__device__ __nv_bfloat16 g_Xlo[BB * SS * EE];
__device__ __nv_bfloat16 g_Qhi[BB * SS * EE];   // projected q/k/v splits
__device__ __nv_bfloat16 g_Qlo[BB * SS * EE];
__device__ __nv_bfloat16 g_Khi[BB * SS * EE];
__device__ __nv_bfloat16 g_Klo[BB * SS * EE];
__device__ __nv_bfloat16 g_Vhi[BB * SS * EE];
__device__ __nv_bfloat16 g_Vlo[BB * SS * EE];
__device__ __nv_bfloat16 g_AThi[BB * SS * EE];  // attention output split
__device__ __nv_bfloat16 g_ATlo[BB * SS * EE];
__device__ __nv_bfloat16 g_Whi[4][EE * EE];     // Wq,Wk,Wv,Wo splits
__device__ __nv_bfloat16 g_Wlo[4][EE * EE];
__device__ float g_maskflag[BB * SS];
__device__ int   g_mask_dtype;

// ---------------- helpers ----------------
__device__ __forceinline__ uint32_t smem_u32(const void* p) {
    uint32_t a;
    asm("{ .reg .u64 t; cvta.to.shared.u64 t, %1; cvt.u32.u64 %0, t; }" : "=r"(a) : "l"(p));
    return a;
}
__device__ __forceinline__ void ldsm4(uint32_t* r, uint32_t addr) {
    asm volatile("ldmatrix.sync.aligned.m8n8.x4.shared.b16 {%0,%1,%2,%3}, [%4];"
        : "=r"(r[0]), "=r"(r[1]), "=r"(r[2]), "=r"(r[3]) : "r"(addr));
}
__device__ __forceinline__ void ldsm4t(uint32_t* r, uint32_t addr) {
    asm volatile("ldmatrix.sync.aligned.m8n8.x4.trans.shared.b16 {%0,%1,%2,%3}, [%4];"
        : "=r"(r[0]), "=r"(r[1]), "=r"(r[2]), "=r"(r[3]) : "r"(addr));
}
__device__ __forceinline__ void mma16816(float* c, const uint32_t* a, uint32_t b0, uint32_t b1) {
    asm volatile(
        "mma.sync.aligned.m16n8k16.row.col.f32.bf16.bf16.f32 "
        "{%0,%1,%2,%3}, {%4,%5,%6,%7}, {%8,%9}, {%0,%1,%2,%3};"
        : "+f"(c[0]), "+f"(c[1]), "+f"(c[2]), "+f"(c[3])
        : "r"(a[0]), "r"(a[1]), "r"(a[2]), "r"(a[3]), "r"(b0), "r"(b1));
}
__device__ __forceinline__ void cpa16(uint32_t saddr, const void* g) {
    asm volatile("cp.async.cg.shared.global [%0], [%1], 16;" :: "r"(saddr), "l"(g));
}
#define CP_COMMIT() asm volatile("cp.async.commit_group;" ::: "memory")
#define CP_WAIT(n)  asm volatile("cp.async.wait_group %0;" :: "n"(n) : "memory")

__device__ __forceinline__ uint32_t pack_hi2(float x, float y) {
    __nv_bfloat162 v = __halves2bfloat162(__float2bfloat16(x), __float2bfloat16(y));
    return *(uint32_t*)&v;
}
__device__ __forceinline__ uint32_t pack_lo2(float x, float y, uint32_t hi) {
    __nv_bfloat162 h = *(__nv_bfloat162*)&hi;
    __nv_bfloat162 v = __halves2bfloat162(
        __float2bfloat16(x - __bfloat162float(h.x)),
        __float2bfloat16(y - __bfloat162float(h.y)));
    return *(uint32_t*)&v;
}

// ---------------- fp32 -> bf16 hi/lo split ----------------
__global__ void split_kernel(const float* __restrict__ src,
                             __nv_bfloat16* __restrict__ hi,
                             __nv_bfloat16* __restrict__ lo, int n4) {
    int i = blockIdx.x * blockDim.x + threadIdx.x;
    if (i >= n4) return;
    float4 v = ((const float4*)src)[i];
    float vv[4] = {v.x, v.y, v.z, v.w};
    __nv_bfloat16 h[4], l[4];
    #pragma unroll
    for (int j = 0; j < 4; ++j) {
        h[j] = __float2bfloat16(vv[j]);
        l[j] = __float2bfloat16(vv[j] - __bfloat162float(h[j]));
    }
    __nv_bfloat162* ph = (__nv_bfloat162*)&hi[(size_t)i * 4];
    __nv_bfloat162* pl = (__nv_bfloat162*)&lo[(size_t)i * 4];
    ph[0] = __halves2bfloat162(h[0], h[1]);
    ph[1] = __halves2bfloat162(h[2], h[3]);
    pl[0] = __halves2bfloat162(l[0], l[1]);
    pl[1] = __halves2bfloat162(l[2], l[3]);
}

// ---------------- key_padding_mask dtype detection ----------------
__global__ void detect_mask_kernel(const void* mask) {
    const unsigned int* w = (const unsigned int*)mask;
    __shared__ int s_f32, s_big;
    if (threadIdx.x == 0) { s_f32 = 0; s_big = 0; }
    __syncthreads();
    int lf = 0, lb = 0;
    for (int i = threadIdx.x; i < 2048; i += blockDim.x) {
        unsigned int v = w[i];
        if (v == 0x3F800000u) lf = 1;
        else if (v > 1u) lb = 1;
    }
    if (lf) atomicOr(&s_f32, 1);
    if (lb) atomicOr(&s_big, 1);
    __syncthreads();
    if (threadIdx.x == 0)
        g_mask_dtype = s_f32 ? 2 : (s_big ? 0 : 1);
}

__global__ void expand_mask_kernel(const void* mask) {
    int i = blockIdx.x * blockDim.x + threadIdx.x;
    if (i >= BB * SS) return;
    int dt = g_mask_dtype;
    bool f;
    if (dt == 0)      f = ((const unsigned char*)mask)[i] != 0;
    else if (dt == 1) f = ((const int*)mask)[i] != 0;
    else              f = ((const float*)mask)[i] != 0.0f;
    g_maskflag[i] = f ? 1.0f : 0.0f;
}

// ---------------- mma.sync GEMM: C = alpha*(A@W^T + bias) ----------------
// 3-term bf16 split, CTA 128x128, 8 warps, warp tile 64x32, K-chunk 32.
// 2-stage cp.async pipeline (this round's single change vs R13).
#define KC 32
#define TS 80
#define SM_A_HI 0
#define SM_A_LO 10240
#define SM_B_HI 20480
#define SM_B_LO 30720
#define GSTG 40960
#define GEMM_SMEM (2 * GSTG)

template <bool SPLIT>
__global__ __launch_bounds__(256, 2)
void gemm_mma_kernel(const __nv_bfloat16* __restrict__ Ahi,
                     const __nv_bfloat16* __restrict__ Alo,
                     const __nv_bfloat16* __restrict__ Whi,
                     const __nv_bfloat16* __restrict__ Wlo,
                     const float* __restrict__ bias,
                     float* __restrict__ C,
                     __nv_bfloat16* __restrict__ Chi,
                     __nv_bfloat16* __restrict__ Clo,
                     float alpha)
{
    extern __shared__ __align__(16) char smem[];
    int tid = threadIdx.x;
    int wid = tid >> 5;
    int lane = tid & 31;
    int m0 = blockIdx.y * 128;
    int n0 = blockIdx.x * 128;
    int wm = wid & 1;
    int wn = wid >> 1;

    float acc[4][4][4];
    #pragma unroll
    for (int mt = 0; mt < 4; ++mt)
        #pragma unroll
        for (int nt = 0; nt < 4; ++nt)
            #pragma unroll
            for (int k = 0; k < 4; ++k) acc[mt][nt][k] = 0.0f;

    uint32_t sb = smem_u32(smem);
    int lr = lane & 7;
    int qq = lane >> 3;
    uint32_t aHiA[4], aLoA[4], bHiA[2], bLoA[2];
    #pragma unroll
    for (int mt = 0; mt < 4; ++mt) {
        int row = wm * 64 + mt * 16 + lr + (qq & 1) * 8;
        uint32_t off = row * TS + (qq >> 1) * 16;
        aHiA[mt] = sb + SM_A_HI + off;
        aLoA[mt] = sb + SM_A_LO + off;
    }
    #pragma unroll
    for (int p = 0; p < 2; ++p) {
        int row = wn * 32 + p * 16 + lr + (qq & 1) * 8;
        uint32_t off = row * TS + (qq >> 1) * 16;
        bHiA[p] = sb + SM_B_HI + off;
        bLoA[p] = sb + SM_B_LO + off;
    }

    int glr = tid >> 2;
    int glj = tid & 3;

    auto prefetchG = [&](int c, uint32_t sbase) {
        int kc = c * KC;
        #pragma unroll
        for (int it = 0; it < 2; ++it) {
            int r = glr + it * 64;
            uint32_t so = sbase + r * TS + glj * 16;
            size_t ga = (size_t)(m0 + r) * EE + kc + glj * 8;
            size_t gb = (size_t)(n0 + r) * EE + kc + glj * 8;
            cpa16(sb + SM_A_HI + so, Ahi + ga);
            cpa16(sb + SM_A_LO + so, Alo + ga);
            cpa16(sb + SM_B_HI + so, Whi + gb);
            cpa16(sb + SM_B_LO + so, Wlo + gb);
        }
    };

    prefetchG(0, 0);
    CP_COMMIT();

    const int NITER = EE / KC;   // 32
    for (int c = 0; c < NITER; ++c) {
        uint32_t cs = (uint32_t)(c & 1) * GSTG;
        if (c + 1 < NITER) {
            prefetchG(c + 1, (uint32_t)((c + 1) & 1) * GSTG);
            CP_COMMIT();
            CP_WAIT(1);
        } else {
            CP_WAIT(0);
        }
        __syncthreads();

        #pragma unroll
        for (int ks = 0; ks < 2; ++ks) {
            uint32_t koB = cs + ks * 32;
            uint32_t aH[4][4], bH[2][4];
            #pragma unroll
            for (int mt = 0; mt < 4; ++mt) ldsm4(aH[mt], aHiA[mt] + koB);
            #pragma unroll
            for (int p = 0; p < 2; ++p) ldsm4(bH[p], bHiA[p] + koB);
            #pragma unroll
            for (int mt = 0; mt < 4; ++mt)
                #pragma unroll
                for (int nt = 0; nt < 4; ++nt)
                    mma16816(acc[mt][nt], aH[mt], bH[nt >> 1][nt & 1], bH[nt >> 1][(nt & 1) + 2]);
            {
                uint32_t bL[2][4];
                #pragma unroll
                for (int p = 0; p < 2; ++p) ldsm4(bL[p], bLoA[p] + koB);
                #pragma unroll
                for (int mt = 0; mt < 4; ++mt)
                    #pragma unroll
                    for (int nt = 0; nt < 4; ++nt)
                        mma16816(acc[mt][nt], aH[mt], bL[nt >> 1][nt & 1], bL[nt >> 1][(nt & 1) + 2]);
            }
            {
                uint32_t aL[4][4];
                #pragma unroll
                for (int mt = 0; mt < 4; ++mt) ldsm4(aL[mt], aLoA[mt] + koB);
                #pragma unroll
                for (int mt = 0; mt < 4; ++mt)
                    #pragma unroll
                    for (int nt = 0; nt < 4; ++nt)
                        mma16816(acc[mt][nt], aL[mt], bH[nt >> 1][nt & 1], bH[nt >> 1][(nt & 1) + 2]);
            }
        }
        __syncthreads();
    }

    int gid = lane >> 2;
    int tig = lane & 3;
    #pragma unroll
    for (int nt = 0; nt < 4; ++nt) {
        int col = n0 + wn * 32 + nt * 8 + tig * 2;
        float b0 = bias[col], b1 = bias[col + 1];
        #pragma unroll
        for (int mt = 0; mt < 4; ++mt) {
            int row = m0 + wm * 64 + mt * 16 + gid;
            float v0 = alpha * (acc[mt][nt][0] + b0);
            float v1 = alpha * (acc[mt][nt][1] + b1);
            float v2 = alpha * (acc[mt][nt][2] + b0);
            float v3 = alpha * (acc[mt][nt][3] + b1);
            if (SPLIT) {
                uint32_t h0 = pack_hi2(v0, v1);
                uint32_t l0 = pack_lo2(v0, v1, h0);
                uint32_t h1 = pack_hi2(v2, v3);
                uint32_t l1 = pack_lo2(v2, v3, h1);
                *(uint32_t*)&Chi[(size_t)row * EE + col] = h0;
                *(uint32_t*)&Clo[(size_t)row * EE + col] = l0;
                *(uint32_t*)&Chi[(size_t)(row + 8) * EE + col] = h1;
                *(uint32_t*)&Clo[(size_t)(row + 8) * EE + col] = l1;
            } else {
                float2 w0 = {v0, v1}, w1 = {v2, v3};
                *(float2*)&C[(size_t)row * EE + col] = w0;
                *(float2*)&C[(size_t)(row + 8) * EE + col] = w1;
            }
        }
    }
}

// ---------------- fused attention (flash, mma.sync bf16-split) ----------------
// CTA: 128 q rows, 8 warps. Key tile 64. K/V (+mask) double-buffered via
// cp.async; attn_bias + attn_mask remain direct LDGs. (identical to R13)
#define ATS 144
#define AK_HI 0
#define AK_LO 9216
#define AV_HI 18432
#define AV_LO 27648
#define A_MSK 36864          // 64 floats = 256 B
#define ASTG  37120
#define ATT_SMEM (2 * ASTG)  // 74240

__global__ __launch_bounds__(256)
void attention_mma_kernel(const float* __restrict__ attn_bias,
                          const float* __restrict__ attn_mask)
{
    extern __shared__ __align__(16) char dsm[];
    uint32_t sb = smem_u32(dsm);

    int tid = threadIdx.x;
    int wid = tid >> 5;
    int lane = tid & 31;
    int gid = lane >> 2;
    int tig = lane & 3;
    int lr = lane & 7;
    int qq = lane >> 3;
    int bh = blockIdx.y;
    int b = bh >> 4, h = bh & 15;
    int q0 = blockIdx.x * 128;
    int wq = wid * 16;

    // ---- stage Q tile (128x64 hi+lo) in stage-0 area, extract fragments ----
    #pragma unroll
    for (int i = 0; i < 4; ++i) {
        int v = tid + i * 256;
        int r = v >> 3;
        int j = v & 7;
        size_t ga = (size_t)(b * SS + q0 + r) * EE + h * DD + j * 8;
        *(uint4*)(dsm + r * ATS + j * 16) = *(const uint4*)(g_Qhi + ga);
        *(uint4*)(dsm + 18432 + r * ATS + j * 16) = *(const uint4*)(g_Qlo + ga);
    }
    __syncthreads();

    uint32_t aQh[4][4], aQl[4][4];
    {
        uint32_t base = (uint32_t)((wq + lr + (qq & 1) * 8) * ATS + (qq >> 1) * 16);
        #pragma unroll
        for (int kc = 0; kc < 4; ++kc) {
            ldsm4(aQh[kc], sb + base + kc * 32);
            ldsm4(aQl[kc], sb + 18432 + base + kc * 32);
        }
    }
    __syncthreads();   // Q reads done before stage-0 prefetch overwrites

    float o[8][4];
    #pragma unroll
    for (int nt = 0; nt < 8; ++nt)
        #pragma unroll
        for (int k = 0; k < 4; ++k) o[nt][k] = 0.0f;
    float m0r = -INFINITY, m1r = -INFINITY, l0r = 0.0f, l1r = 0.0f;

    int qr0 = q0 + wq + gid;
    const float* biasRow0 = attn_bias + ((size_t)(b * HH + h) * SS + qr0) * SS;
    const float* biasRow1 = biasRow0 + 8 * SS;
    const float* amRow0 = attn_mask + (size_t)qr0 * SS;
    const float* amRow1 = amRow0 + 8 * SS;

    uint32_t kfb = (uint32_t)((lr + (qq & 1) * 8) * ATS + (qq >> 1) * 16);
    int vkey = ((lane >> 3) & 1) * 8 + lr;
    int vd = (lane >> 4) * 8;

    auto prefetchA = [&](int nk0, uint32_t nbase) {
        uint32_t nb = sb + nbase;
        #pragma unroll
        for (int i = 0; i < 8; ++i) {
            int v = tid + i * 256;
            int arr = v >> 9;
            int rem = v & 511;
            int r = rem >> 3;
            int j = rem & 7;
            const __nv_bfloat16* src = (arr == 0) ? g_Khi : (arr == 1) ? g_Klo
                                     : (arr == 2) ? g_Vhi : g_Vlo;
            cpa16(nb + arr * 9216 + r * ATS + j * 16,
                  src + (size_t)(b * SS + nk0 + r) * EE + h * DD + j * 8);
        }
        if (tid < 16)
            cpa16(nb + A_MSK + tid * 16, g_maskflag + b * SS + nk0 + tid * 4);
    };

    prefetchA(0, 0);
    CP_COMMIT();

    for (int t = 0; t < SS / 64; ++t) {
        int k0 = t * 64;
        uint32_t cs = (uint32_t)(t & 1) * ASTG;
        if (t + 1 < SS / 64) {
            prefetchA(k0 + 64, (uint32_t)((t + 1) & 1) * ASTG);
            CP_COMMIT();
            CP_WAIT(1);
        } else {
            CP_WAIT(0);
        }
        __syncthreads();

        const float* maskS = (const float*)(dsm + cs + A_MSK);

        // ---- S = Q K^T (3-term split), 8-reg K live set ----
        float s[8][4];
        #pragma unroll
        for (int nt = 0; nt < 8; ++nt)
            #pragma unroll
            for (int k = 0; k < 4; ++k) s[nt][k] = 0.0f;

        #pragma unroll
        for (int kc = 0; kc < 4; ++kc) {
            uint32_t koB = cs + kfb + kc * 32;
            #pragma unroll
            for (int ng = 0; ng < 4; ++ng) {
                uint32_t bKh[4], bKl[4];
                ldsm4(bKh, sb + AK_HI + (uint32_t)(ng * 16 * ATS) + koB);
                ldsm4(bKl, sb + AK_LO + (uint32_t)(ng * 16 * ATS) + koB);
                int nt0 = 2 * ng, nt1 = 2 * ng + 1;
                mma16816(s[nt0], aQh[kc], bKh[0], bKh[2]);
                mma16816(s[nt1], aQh[kc], bKh[1], bKh[3]);
                mma16816(s[nt0], aQh[kc], bKl[0], bKl[2]);
                mma16816(s[nt1], aQh[kc], bKl[1], bKl[3]);
                mma16816(s[nt0], aQl[kc], bKh[0], bKh[2]);
                mma16816(s[nt1], aQl[kc], bKh[1], bKh[3]);
            }
        }

        // ---- bias + attn_mask (direct LDG) + padding mask (smem) ----
        #pragma unroll
        for (int nt = 0; nt < 8; ++nt) {
            int col = nt * 8 + tig * 2;
            float2 bb0 = *(const float2*)&biasRow0[k0 + col];
            float2 bb1 = *(const float2*)&biasRow1[k0 + col];
            float2 am0 = *(const float2*)&amRow0[k0 + col];
            float2 am1 = *(const float2*)&amRow1[k0 + col];
            float mf0 = maskS[col], mf1 = maskS[col + 1];
            s[nt][0] = (mf0 > 0.5f) ? NEG_INF : s[nt][0] + bb0.x + am0.x;
            s[nt][1] = (mf1 > 0.5f) ? NEG_INF : s[nt][1] + bb0.y + am0.y;
            s[nt][2] = (mf0 > 0.5f) ? NEG_INF : s[nt][2] + bb1.x + am1.x;
            s[nt][3] = (mf1 > 0.5f) ? NEG_INF : s[nt][3] + bb1.y + am1.y;
        }

        // ---- online softmax (rows gid and gid+8) ----
        float mx0 = -INFINITY, mx1 = -INFINITY;
        #pragma unroll
        for (int nt = 0; nt < 8; ++nt) {
            mx0 = fmaxf(mx0, fmaxf(s[nt][0], s[nt][1]));
            mx1 = fmaxf(mx1, fmaxf(s[nt][2], s[nt][3]));
        }
        mx0 = fmaxf(mx0, __shfl_xor_sync(0xffffffffu, mx0, 1));
        mx0 = fmaxf(mx0, __shfl_xor_sync(0xffffffffu, mx0, 2));
        mx1 = fmaxf(mx1, __shfl_xor_sync(0xffffffffu, mx1, 1));
        mx1 = fmaxf(mx1, __shfl_xor_sync(0xffffffffu, mx1, 2));
        float mn0 = fmaxf(m0r, mx0), mn1 = fmaxf(m1r, mx1);
        float sc0 = __expf(m0r - mn0), sc1 = __expf(m1r - mn1);
        float rs0 = 0.0f, rs1 = 0.0f;
        #pragma unroll
        for (int nt = 0; nt < 8; ++nt) {
            s[nt][0] = __expf(s[nt][0] - mn0);
            s[nt][1] = __expf(s[nt][1] - mn0);
            s[nt][2] = __expf(s[nt][2] - mn1);
            s[nt][3] = __expf(s[nt][3] - mn1);
            rs0 += s[nt][0] + s[nt][1];
            rs1 += s[nt][2] + s[nt][3];
        }
        rs0 += __shfl_xor_sync(0xffffffffu, rs0, 1);
        rs0 += __shfl_xor_sync(0xffffffffu, rs0, 2);
        rs1 += __shfl_xor_sync(0xffffffffu, rs1, 1);
        rs1 += __shfl_xor_sync(0xffffffffu, rs1, 2);
        l0r = l0r * sc0 + rs0;
        l1r = l1r * sc1 + rs1;
        m0r = mn0; m1r = mn1;
        #pragma unroll
        for (int nt = 0; nt < 8; ++nt) {
            o[nt][0] *= sc0; o[nt][1] *= sc0;
            o[nt][2] *= sc1; o[nt][3] *= sc1;
        }

        // ---- pack P hi/lo as A-fragments ----
        uint32_t ph[4][4], pl[4][4];
        #pragma unroll
        for (int kc = 0; kc < 4; ++kc) {
            int n0t = 2 * kc, n1t = 2 * kc + 1;
            ph[kc][0] = pack_hi2(s[n0t][0], s[n0t][1]);
            pl[kc][0] = pack_lo2(s[n0t][0], s[n0t][1], ph[kc][0]);
            ph[kc][1] = pack_hi2(s[n0t][2], s[n0t][3]);
            pl[kc][1] = pack_lo2(s[n0t][2], s[n0t][3], ph[kc][1]);
            ph[kc][2] = pack_hi2(s[n1t][0], s[n1t][1]);
            pl[kc][2] = pack_lo2(s[n1t][0], s[n1t][1], ph[kc][2]);
            ph[kc][3] = pack_hi2(s[n1t][2], s[n1t][3]);
            pl[kc][3] = pack_lo2(s[n1t][2], s[n1t][3], ph[kc][3]);
        }

        // ---- O += P V (3-term split), 8-reg V live set ----
        #pragma unroll
        for (int kc = 0; kc < 4; ++kc) {
            #pragma unroll
            for (int dg = 0; dg < 4; ++dg) {
                uint32_t off = cs + (uint32_t)((kc * 16 + vkey) * ATS + (dg * 16 + vd) * 2);
                uint32_t vh[4], vl[4];
                ldsm4t(vh, sb + AV_HI + off);
                ldsm4t(vl, sb + AV_LO + off);
                int nt0 = 2 * dg, nt1 = 2 * dg + 1;
                mma16816(o[nt0], ph[kc], vh[0], vh[1]);
                mma16816(o[nt0], ph[kc], vl[0], vl[1]);
                mma16816(o[nt0], pl[kc], vh[0], vh[1]);
                mma16816(o[nt1], ph[kc], vh[2], vh[3]);
                mma16816(o[nt1], ph[kc], vl[2], vl[3]);
                mma16816(o[nt1], pl[kc], vh[2], vh[3]);
            }
        }
        __syncthreads();
    }

    // ---- normalize + emit bf16 hi/lo split ----
    float inv0 = 1.0f / l0r, inv1 = 1.0f / l1r;
    size_t row0 = (size_t)(b * SS + qr0) * EE + h * DD;
    size_t row1 = row0 + 8 * EE;
    #pragma unroll
    for (int nt = 0; nt < 8; ++nt) {
        int col = nt * 8 + tig * 2;
        float v0 = o[nt][0] * inv0, v1 = o[nt][1] * inv0;
        float v2 = o[nt][2] * inv1, v3 = o[nt][3] * inv1;
        uint32_t h0 = pack_hi2(v0, v1);
        uint32_t l0 = pack_lo2(v0, v1, h0);
        uint32_t h1 = pack_hi2(v2, v3);
        uint32_t l1 = pack_lo2(v2, v3, h1);
        *(uint32_t*)&g_AThi[row0 + col] = h0;
        *(uint32_t*)&g_ATlo[row0 + col] = l0;
        *(uint32_t*)&g_AThi[row1 + col] = h1;
        *(uint32_t*)&g_ATlo[row1 + col] = l1;
    }
}

// ---------------- launch ----------------
extern "C" void kernel_launch(void* const* d_in, const int* in_sizes, int n_in,
                              void* d_out, int out_size) {
    const float* query     = (const float*)d_in[0];
    const float* attn_bias = (const float*)d_in[3];
    const void*  kpm       = d_in[4];
    const float* attn_mask = (const float*)d_in[5];
    const float* Wq = (const float*)d_in[9];
    const float* bq = (const float*)d_in[10];
    const float* Wk = (const float*)d_in[11];
    const float* bk = (const float*)d_in[12];
    const float* Wv = (const float*)d_in[13];
    const float* bv = (const float*)d_in[14];
    const float* Wo = (const float*)d_in[15];
    const float* bo = (const float*)d_in[16];
    float* out = (float*)d_out;

    __nv_bfloat16 *gXhi, *gXlo, *gQhi, *gQlo, *gKhi, *gKlo, *gVhi, *gVlo,
                  *gAThi, *gATlo, *gWhi, *gWlo;
    cudaGetSymbolAddress((void**)&gXhi, g_Xhi);
    cudaGetSymbolAddress((void**)&gXlo, g_Xlo);
    cudaGetSymbolAddress((void**)&gQhi, g_Qhi);
    cudaGetSymbolAddress((void**)&gQlo, g_Qlo);
    cudaGetSymbolAddress((void**)&gKhi, g_Khi);
    cudaGetSymbolAddress((void**)&gKlo, g_Klo);
    cudaGetSymbolAddress((void**)&gVhi, g_Vhi);
    cudaGetSymbolAddress((void**)&gVlo, g_Vlo);
    cudaGetSymbolAddress((void**)&gAThi, g_AThi);
    cudaGetSymbolAddress((void**)&gATlo, g_ATlo);
    cudaGetSymbolAddress((void**)&gWhi, g_Whi);
    cudaGetSymbolAddress((void**)&gWlo, g_Wlo);

    cudaFuncSetAttribute(gemm_mma_kernel<true>,
                         cudaFuncAttributeMaxDynamicSharedMemorySize, GEMM_SMEM);
    cudaFuncSetAttribute(gemm_mma_kernel<false>,
                         cudaFuncAttributeMaxDynamicSharedMemorySize, GEMM_SMEM);
    cudaFuncSetAttribute(attention_mma_kernel,
                         cudaFuncAttributeMaxDynamicSharedMemorySize, ATT_SMEM);

    const int nq4 = BB * SS * EE / 4;
    const int nw4 = EE * EE / 4;
    split_kernel<<<(nq4 + 255) / 256, 256>>>(query, gXhi, gXlo, nq4);
    split_kernel<<<(nw4 + 255) / 256, 256>>>(Wq, gWhi + 0 * (size_t)EE * EE, gWlo + 0 * (size_t)EE * EE, nw4);
    split_kernel<<<(nw4 + 255) / 256, 256>>>(Wk, gWhi + 1 * (size_t)EE * EE, gWlo + 1 * (size_t)EE * EE, nw4);
    split_kernel<<<(nw4 + 255) / 256, 256>>>(Wv, gWhi + 2 * (size_t)EE * EE, gWlo + 2 * (size_t)EE * EE, nw4);
    split_kernel<<<(nw4 + 255) / 256, 256>>>(Wo, gWhi + 3 * (size_t)EE * EE, gWlo + 3 * (size_t)EE * EE, nw4);

    detect_mask_kernel<<<1, 256>>>(kpm);
    expand_mask_kernel<<<(BB * SS + 255) / 256, 256>>>(kpm);

    dim3 ggrid(EE / 128, BB * SS / 128);   // (8, 64)
    const float scaling = 0.125f;          // D^-0.5

    gemm_mma_kernel<true><<<ggrid, 256, GEMM_SMEM>>>(gXhi, gXlo,
        gWhi + 0 * (size_t)EE * EE, gWlo + 0 * (size_t)EE * EE, bq,
        nullptr, gQhi, gQlo, scaling);
    gemm_mma_kernel<true><<<ggrid, 256, GEMM_SMEM>>>(gXhi, gXlo,
        gWhi + 1 * (size_t)EE * EE, gWlo + 1 * (size_t)EE * EE, bk,
        nullptr, gKhi, gKlo, 1.0f);
    gemm_mma_kernel<true><<<ggrid, 256, GEMM_SMEM>>>(gXhi, gXlo,
        gWhi + 2 * (size_t)EE * EE, gWlo + 2 * (size_t)EE * EE, bv,
        nullptr, gVhi, gVlo, 1.0f);

    attention_mma_kernel<<<dim3(SS / 128, BB * HH), 256, ATT_SMEM>>>(attn_bias, attn_mask);

    gemm_mma_kernel<false><<<ggrid, 256, GEMM_SMEM>>>(gAThi, gATlo,
        gWhi + 3 * (size_t)EE * EE, gWlo + 3 * (size_t)EE * EE, bo,
        out, nullptr, nullptr, 1.0f);
}

// round 15
// speedup vs baseline: 1.5379x; 1.1022x over previous
#include <cuda_runtime.h>
#include <cuda_bf16.h>
#include <cstdint>
#include <cstddef>

#define BB 8
#define SS 1024
#define EE 1024
#define HH 16
#define DD 64
#define NEG_INF (-3.402823466e38f)

// ---------------- scratch (no allocations allowed) ----------------
__device__ __nv_bfloat16 g_Xhi[BB * SS * EE];   // query split
__device__ __nv_bfloat16 g_Xlo[BB * SS * EE];
__device__ __nv_bfloat16 g_Qhi[BB * SS * EE];   // projected q/k/v splits
__device__ __nv_bfloat16 g_Qlo[BB * SS * EE];
__device__ __nv_bfloat16 g_Khi[BB * SS * EE];
__device__ __nv_bfloat16 g_Klo[BB * SS * EE];
__device__ __nv_bfloat16 g_Vhi[BB * SS * EE];
__device__ __nv_bfloat16 g_Vlo[BB * SS * EE];
__device__ __nv_bfloat16 g_AThi[BB * SS * EE];  // attention output split
__device__ __nv_bfloat16 g_ATlo[BB * SS * EE];
__device__ __nv_bfloat16 g_Whi[4][EE * EE];     // Wq,Wk,Wv,Wo splits
__device__ __nv_bfloat16 g_Wlo[4][EE * EE];
__device__ float g_maskflag[BB * SS];
__device__ int   g_mask_dtype;

// ---------------- helpers ----------------
__device__ __forceinline__ uint32_t smem_u32(const void* p) {
    uint32_t a;
    asm("{ .reg .u64 t; cvta.to.shared.u64 t, %1; cvt.u32.u64 %0, t; }" : "=r"(a) : "l"(p));
    return a;
}
__device__ __forceinline__ void ldsm4(uint32_t* r, uint32_t addr) {
    asm volatile("ldmatrix.sync.aligned.m8n8.x4.shared.b16 {%0,%1,%2,%3}, [%4];"
        : "=r"(r[0]), "=r"(r[1]), "=r"(r[2]), "=r"(r[3]) : "r"(addr));
}
__device__ __forceinline__ void ldsm4t(uint32_t* r, uint32_t addr) {
    asm volatile("ldmatrix.sync.aligned.m8n8.x4.trans.shared.b16 {%0,%1,%2,%3}, [%4];"
        : "=r"(r[0]), "=r"(r[1]), "=r"(r[2]), "=r"(r[3]) : "r"(addr));
}
__device__ __forceinline__ void mma16816(float* c, const uint32_t* a, uint32_t b0, uint32_t b1) {
    asm volatile(
        "mma.sync.aligned.m16n8k16.row.col.f32.bf16.bf16.f32 "
        "{%0,%1,%2,%3}, {%4,%5,%6,%7}, {%8,%9}, {%0,%1,%2,%3};"
        : "+f"(c[0]), "+f"(c[1]), "+f"(c[2]), "+f"(c[3])
        : "r"(a[0]), "r"(a[1]), "r"(a[2]), "r"(a[3]), "r"(b0), "r"(b1));
}
__device__ __forceinline__ void cpa16(uint32_t saddr, const void* g) {
    asm volatile("cp.async.cg.shared.global [%0], [%1], 16;" :: "r"(saddr), "l"(g));
}
#define CP_COMMIT() asm volatile("cp.async.commit_group;" ::: "memory")
#define CP_WAIT(n)  asm volatile("cp.async.wait_group %0;" :: "n"(n) : "memory")

__device__ __forceinline__ uint32_t pack_hi2(float x, float y) {
    __nv_bfloat162 v = __halves2bfloat162(__float2bfloat16(x), __float2bfloat16(y));
    return *(uint32_t*)&v;
}
__device__ __forceinline__ uint32_t pack_lo2(float x, float y, uint32_t hi) {
    __nv_bfloat162 h = *(__nv_bfloat162*)&hi;
    __nv_bfloat162 v = __halves2bfloat162(
        __float2bfloat16(x - __bfloat162float(h.x)),
        __float2bfloat16(y - __bfloat162float(h.y)));
    return *(uint32_t*)&v;
}

// ---------------- fp32 -> bf16 hi/lo split ----------------
__global__ void split_kernel(const float* __restrict__ src,
                             __nv_bfloat16* __restrict__ hi,
                             __nv_bfloat16* __restrict__ lo, int n4) {
    int i = blockIdx.x * blockDim.x + threadIdx.x;
    if (i >= n4) return;
    float4 v = ((const float4*)src)[i];
    float vv[4] = {v.x, v.y, v.z, v.w};
    __nv_bfloat16 h[4], l[4];
    #pragma unroll
    for (int j = 0; j < 4; ++j) {
        h[j] = __float2bfloat16(vv[j]);
        l[j] = __float2bfloat16(vv[j] - __bfloat162float(h[j]));
    }
    __nv_bfloat162* ph = (__nv_bfloat162*)&hi[(size_t)i * 4];
    __nv_bfloat162* pl = (__nv_bfloat162*)&lo[(size_t)i * 4];
    ph[0] = __halves2bfloat162(h[0], h[1]);
    ph[1] = __halves2bfloat162(h[2], h[3]);
    pl[0] = __halves2bfloat162(l[0], l[1]);
    pl[1] = __halves2bfloat162(l[2], l[3]);
}

// ---------------- key_padding_mask dtype detection ----------------
__global__ void detect_mask_kernel(const void* mask) {
    const unsigned int* w = (const unsigned int*)mask;
    __shared__ int s_f32, s_big;
    if (threadIdx.x == 0) { s_f32 = 0; s_big = 0; }
    __syncthreads();
    int lf = 0, lb = 0;
    for (int i = threadIdx.x; i < 2048; i += blockDim.x) {
        unsigned int v = w[i];
        if (v == 0x3F800000u) lf = 1;
        else if (v > 1u) lb = 1;
    }
    if (lf) atomicOr(&s_f32, 1);
    if (lb) atomicOr(&s_big, 1);
    __syncthreads();
    if (threadIdx.x == 0)
        g_mask_dtype = s_f32 ? 2 : (s_big ? 0 : 1);
}

__global__ void expand_mask_kernel(const void* mask) {
    int i = blockIdx.x * blockDim.x + threadIdx.x;
    if (i >= BB * SS) return;
    int dt = g_mask_dtype;
    bool f;
    if (dt == 0)      f = ((const unsigned char*)mask)[i] != 0;
    else if (dt == 1) f = ((const int*)mask)[i] != 0;
    else              f = ((const float*)mask)[i] != 0.0f;
    g_maskflag[i] = f ? 1.0f : 0.0f;
}

// ---------------- mma.sync GEMM: C = alpha*(A@W^T + bias) ----------------
// 3-term bf16 split, CTA 128x128, 8 warps, warp tile 64x32, K-chunk 32.
// 2-stage cp.async pipeline (identical to R14).
#define KC 32
#define TS 80
#define SM_A_HI 0
#define SM_A_LO 10240
#define SM_B_HI 20480
#define SM_B_LO 30720
#define GSTG 40960
#define GEMM_SMEM (2 * GSTG)

template <bool SPLIT>
__global__ __launch_bounds__(256, 2)
void gemm_mma_kernel(const __nv_bfloat16* __restrict__ Ahi,
                     const __nv_bfloat16* __restrict__ Alo,
                     const __nv_bfloat16* __restrict__ Whi,
                     const __nv_bfloat16* __restrict__ Wlo,
                     const float* __restrict__ bias,
                     float* __restrict__ C,
                     __nv_bfloat16* __restrict__ Chi,
                     __nv_bfloat16* __restrict__ Clo,
                     float alpha)
{
    extern __shared__ __align__(16) char smem[];
    int tid = threadIdx.x;
    int wid = tid >> 5;
    int lane = tid & 31;
    int m0 = blockIdx.y * 128;
    int n0 = blockIdx.x * 128;
    int wm = wid & 1;
    int wn = wid >> 1;

    float acc[4][4][4];
    #pragma unroll
    for (int mt = 0; mt < 4; ++mt)
        #pragma unroll
        for (int nt = 0; nt < 4; ++nt)
            #pragma unroll
            for (int k = 0; k < 4; ++k) acc[mt][nt][k] = 0.0f;

    uint32_t sb = smem_u32(smem);
    int lr = lane & 7;
    int qq = lane >> 3;
    uint32_t aHiA[4], aLoA[4], bHiA[2], bLoA[2];
    #pragma unroll
    for (int mt = 0; mt < 4; ++mt) {
        int row = wm * 64 + mt * 16 + lr + (qq & 1) * 8;
        uint32_t off = row * TS + (qq >> 1) * 16;
        aHiA[mt] = sb + SM_A_HI + off;
        aLoA[mt] = sb + SM_A_LO + off;
    }
    #pragma unroll
    for (int p = 0; p < 2; ++p) {
        int row = wn * 32 + p * 16 + lr + (qq & 1) * 8;
        uint32_t off = row * TS + (qq >> 1) * 16;
        bHiA[p] = sb + SM_B_HI + off;
        bLoA[p] = sb + SM_B_LO + off;
    }

    int glr = tid >> 2;
    int glj = tid & 3;

    auto prefetchG = [&](int c, uint32_t sbase) {
        int kc = c * KC;
        #pragma unroll
        for (int it = 0; it < 2; ++it) {
            int r = glr + it * 64;
            uint32_t so = sbase + r * TS + glj * 16;
            size_t ga = (size_t)(m0 + r) * EE + kc + glj * 8;
            size_t gb = (size_t)(n0 + r) * EE + kc + glj * 8;
            cpa16(sb + SM_A_HI + so, Ahi + ga);
            cpa16(sb + SM_A_LO + so, Alo + ga);
            cpa16(sb + SM_B_HI + so, Whi + gb);
            cpa16(sb + SM_B_LO + so, Wlo + gb);
        }
    };

    prefetchG(0, 0);
    CP_COMMIT();

    const int NITER = EE / KC;   // 32
    for (int c = 0; c < NITER; ++c) {
        uint32_t cs = (uint32_t)(c & 1) * GSTG;
        if (c + 1 < NITER) {
            prefetchG(c + 1, (uint32_t)((c + 1) & 1) * GSTG);
            CP_COMMIT();
            CP_WAIT(1);
        } else {
            CP_WAIT(0);
        }
        __syncthreads();

        #pragma unroll
        for (int ks = 0; ks < 2; ++ks) {
            uint32_t koB = cs + ks * 32;
            uint32_t aH[4][4], bH[2][4];
            #pragma unroll
            for (int mt = 0; mt < 4; ++mt) ldsm4(aH[mt], aHiA[mt] + koB);
            #pragma unroll
            for (int p = 0; p < 2; ++p) ldsm4(bH[p], bHiA[p] + koB);
            #pragma unroll
            for (int mt = 0; mt < 4; ++mt)
                #pragma unroll
                for (int nt = 0; nt < 4; ++nt)
                    mma16816(acc[mt][nt], aH[mt], bH[nt >> 1][nt & 1], bH[nt >> 1][(nt & 1) + 2]);
            {
                uint32_t bL[2][4];
                #pragma unroll
                for (int p = 0; p < 2; ++p) ldsm4(bL[p], bLoA[p] + koB);
                #pragma unroll
                for (int mt = 0; mt < 4; ++mt)
                    #pragma unroll
                    for (int nt = 0; nt < 4; ++nt)
                        mma16816(acc[mt][nt], aH[mt], bL[nt >> 1][nt & 1], bL[nt >> 1][(nt & 1) + 2]);
            }
            {
                uint32_t aL[4][4];
                #pragma unroll
                for (int mt = 0; mt < 4; ++mt) ldsm4(aL[mt], aLoA[mt] + koB);
                #pragma unroll
                for (int mt = 0; mt < 4; ++mt)
                    #pragma unroll
                    for (int nt = 0; nt < 4; ++nt)
                        mma16816(acc[mt][nt], aL[mt], bH[nt >> 1][nt & 1], bH[nt >> 1][(nt & 1) + 2]);
            }
        }
        __syncthreads();
    }

    int gid = lane >> 2;
    int tig = lane & 3;
    #pragma unroll
    for (int nt = 0; nt < 4; ++nt) {
        int col = n0 + wn * 32 + nt * 8 + tig * 2;
        float b0 = bias[col], b1 = bias[col + 1];
        #pragma unroll
        for (int mt = 0; mt < 4; ++mt) {
            int row = m0 + wm * 64 + mt * 16 + gid;
            float v0 = alpha * (acc[mt][nt][0] + b0);
            float v1 = alpha * (acc[mt][nt][1] + b1);
            float v2 = alpha * (acc[mt][nt][2] + b0);
            float v3 = alpha * (acc[mt][nt][3] + b1);
            if (SPLIT) {
                uint32_t h0 = pack_hi2(v0, v1);
                uint32_t l0 = pack_lo2(v0, v1, h0);
                uint32_t h1 = pack_hi2(v2, v3);
                uint32_t l1 = pack_lo2(v2, v3, h1);
                *(uint32_t*)&Chi[(size_t)row * EE + col] = h0;
                *(uint32_t*)&Clo[(size_t)row * EE + col] = l0;
                *(uint32_t*)&Chi[(size_t)(row + 8) * EE + col] = h1;
                *(uint32_t*)&Clo[(size_t)(row + 8) * EE + col] = l1;
            } else {
                float2 w0 = {v0, v1}, w1 = {v2, v3};
                *(float2*)&C[(size_t)row * EE + col] = w0;
                *(float2*)&C[(size_t)(row + 8) * EE + col] = w1;
            }
        }
    }
}

// ---------------- fused attention (flash, mma.sync bf16-split) ----------------
// CTA: 128 q rows, 8 warps. Key tile 64. K/V (+mask) double-buffered via
// cp.async. THIS ROUND: Q fragments live in dedicated smem (reloaded per
// tile via ldmatrix) instead of 32 resident registers; launch_bounds(256,2)
// -> 2 CTAs/SM for latency hiding.
#define ATS 144
#define QH_OFF 0
#define QL_OFF 18432
#define STG0   36864          // first stage base
#define AK_HI 0               // offsets within a stage
#define AK_LO 9216
#define AV_HI 18432
#define AV_LO 27648
#define A_MSK 36864           // 64 floats = 256 B
#define ASTG  37120
#define ATT_SMEM (STG0 + 2 * ASTG)   // 111104

__global__ __launch_bounds__(256, 2)
void attention_mma_kernel(const float* __restrict__ attn_bias,
                          const float* __restrict__ attn_mask)
{
    extern __shared__ __align__(16) char dsm[];
    uint32_t sb = smem_u32(dsm);

    int tid = threadIdx.x;
    int wid = tid >> 5;
    int lane = tid & 31;
    int gid = lane >> 2;
    int tig = lane & 3;
    int lr = lane & 7;
    int qq = lane >> 3;
    int bh = blockIdx.y;
    int b = bh >> 4, h = bh & 15;
    int q0 = blockIdx.x * 128;
    int wq = wid * 16;

    // ---- kick off stage-0 K/V prefetch first (overlaps with Q staging) ----
    const float* biasRow0 = attn_bias + ((size_t)(b * HH + h) * SS + q0 + wq + gid) * SS;
    const float* biasRow1 = biasRow0 + 8 * SS;
    const float* amRow0 = attn_mask + (size_t)(q0 + wq + gid) * SS;
    const float* amRow1 = amRow0 + 8 * SS;

    auto prefetchA = [&](int nk0, uint32_t nbase) {
        uint32_t nb = sb + nbase;
        #pragma unroll
        for (int i = 0; i < 8; ++i) {
            int v = tid + i * 256;
            int arr = v >> 9;
            int rem = v & 511;
            int r = rem >> 3;
            int j = rem & 7;
            const __nv_bfloat16* src = (arr == 0) ? g_Khi : (arr == 1) ? g_Klo
                                     : (arr == 2) ? g_Vhi : g_Vlo;
            cpa16(nb + arr * 9216 + r * ATS + j * 16,
                  src + (size_t)(b * SS + nk0 + r) * EE + h * DD + j * 8);
        }
        if (tid < 16)
            cpa16(nb + A_MSK + tid * 16, g_maskflag + b * SS + nk0 + tid * 4);
    };

    prefetchA(0, STG0);
    CP_COMMIT();

    // ---- stage Q tile (128x64 hi+lo) into dedicated region ----
    #pragma unroll
    for (int i = 0; i < 4; ++i) {
        int v = tid + i * 256;
        int r = v >> 3;
        int j = v & 7;
        size_t ga = (size_t)(b * SS + q0 + r) * EE + h * DD + j * 8;
        *(uint4*)(dsm + QH_OFF + r * ATS + j * 16) = *(const uint4*)(g_Qhi + ga);
        *(uint4*)(dsm + QL_OFF + r * ATS + j * 16) = *(const uint4*)(g_Qlo + ga);
    }

    float o[8][4];
    #pragma unroll
    for (int nt = 0; nt < 8; ++nt)
        #pragma unroll
        for (int k = 0; k < 4; ++k) o[nt][k] = 0.0f;
    float m0r = -INFINITY, m1r = -INFINITY, l0r = 0.0f, l1r = 0.0f;

    uint32_t qfb = (uint32_t)((wq + lr + (qq & 1) * 8) * ATS + (qq >> 1) * 16);
    uint32_t kfb = (uint32_t)((lr + (qq & 1) * 8) * ATS + (qq >> 1) * 16);
    int vkey = ((lane >> 3) & 1) * 8 + lr;
    int vd = (lane >> 4) * 8;

    for (int t = 0; t < SS / 64; ++t) {
        int k0 = t * 64;
        uint32_t cs = STG0 + (uint32_t)(t & 1) * ASTG;
        if (t + 1 < SS / 64) {
            prefetchA(k0 + 64, STG0 + (uint32_t)((t + 1) & 1) * ASTG);
            CP_COMMIT();
            CP_WAIT(1);
        } else {
            CP_WAIT(0);
        }
        __syncthreads();   // also covers the Q stores on t==0

        const float* maskS = (const float*)(dsm + cs + A_MSK);

        // ---- S = Q K^T (3-term split); Q fragments re-loaded from smem ----
        float s[8][4];
        #pragma unroll
        for (int nt = 0; nt < 8; ++nt)
            #pragma unroll
            for (int k = 0; k < 4; ++k) s[nt][k] = 0.0f;

        #pragma unroll
        for (int kc = 0; kc < 4; ++kc) {
            uint32_t aQh[4], aQl[4];
            ldsm4(aQh, sb + QH_OFF + qfb + kc * 32);
            ldsm4(aQl, sb + QL_OFF + qfb + kc * 32);
            uint32_t koB = cs + kfb + kc * 32;
            #pragma unroll
            for (int ng = 0; ng < 4; ++ng) {
                uint32_t bKh[4], bKl[4];
                ldsm4(bKh, sb + AK_HI + (uint32_t)(ng * 16 * ATS) + koB);
                ldsm4(bKl, sb + AK_LO + (uint32_t)(ng * 16 * ATS) + koB);
                int nt0 = 2 * ng, nt1 = 2 * ng + 1;
                mma16816(s[nt0], aQh, bKh[0], bKh[2]);
                mma16816(s[nt1], aQh, bKh[1], bKh[3]);
                mma16816(s[nt0], aQh, bKl[0], bKl[2]);
                mma16816(s[nt1], aQh, bKl[1], bKl[3]);
                mma16816(s[nt0], aQl, bKh[0], bKh[2]);
                mma16816(s[nt1], aQl, bKh[1], bKh[3]);
            }
        }

        // ---- bias + attn_mask (direct LDG) + padding mask (smem) ----
        #pragma unroll
        for (int nt = 0; nt < 8; ++nt) {
            int col = nt * 8 + tig * 2;
            float2 bb0 = *(const float2*)&biasRow0[k0 + col];
            float2 bb1 = *(const float2*)&biasRow1[k0 + col];
            float2 am0 = *(const float2*)&amRow0[k0 + col];
            float2 am1 = *(const float2*)&amRow1[k0 + col];
            float mf0 = maskS[col], mf1 = maskS[col + 1];
            s[nt][0] = (mf0 > 0.5f) ? NEG_INF : s[nt][0] + bb0.x + am0.x;
            s[nt][1] = (mf1 > 0.5f) ? NEG_INF : s[nt][1] + bb0.y + am0.y;
            s[nt][2] = (mf0 > 0.5f) ? NEG_INF : s[nt][2] + bb1.x + am1.x;
            s[nt][3] = (mf1 > 0.5f) ? NEG_INF : s[nt][3] + bb1.y + am1.y;
        }

        // ---- online softmax (rows gid and gid+8) ----
        float mx0 = -INFINITY, mx1 = -INFINITY;
        #pragma unroll
        for (int nt = 0; nt < 8; ++nt) {
            mx0 = fmaxf(mx0, fmaxf(s[nt][0], s[nt][1]));
            mx1 = fmaxf(mx1, fmaxf(s[nt][2], s[nt][3]));
        }
        mx0 = fmaxf(mx0, __shfl_xor_sync(0xffffffffu, mx0, 1));
        mx0 = fmaxf(mx0, __shfl_xor_sync(0xffffffffu, mx0, 2));
        mx1 = fmaxf(mx1, __shfl_xor_sync(0xffffffffu, mx1, 1));
        mx1 = fmaxf(mx1, __shfl_xor_sync(0xffffffffu, mx1, 2));
        float mn0 = fmaxf(m0r, mx0), mn1 = fmaxf(m1r, mx1);
        float sc0 = __expf(m0r - mn0), sc1 = __expf(m1r - mn1);
        float rs0 = 0.0f, rs1 = 0.0f;
        #pragma unroll
        for (int nt = 0; nt < 8; ++nt) {
            s[nt][0] = __expf(s[nt][0] - mn0);
            s[nt][1] = __expf(s[nt][1] - mn0);
            s[nt][2] = __expf(s[nt][2] - mn1);
            s[nt][3] = __expf(s[nt][3] - mn1);
            rs0 += s[nt][0] + s[nt][1];
            rs1 += s[nt][2] + s[nt][3];
        }
        rs0 += __shfl_xor_sync(0xffffffffu, rs0, 1);
        rs0 += __shfl_xor_sync(0xffffffffu, rs0, 2);
        rs1 += __shfl_xor_sync(0xffffffffu, rs1, 1);
        rs1 += __shfl_xor_sync(0xffffffffu, rs1, 2);
        l0r = l0r * sc0 + rs0;
        l1r = l1r * sc1 + rs1;
        m0r = mn0; m1r = mn1;
        #pragma unroll
        for (int nt = 0; nt < 8; ++nt) {
            o[nt][0] *= sc0; o[nt][1] *= sc0;
            o[nt][2] *= sc1; o[nt][3] *= sc1;
        }

        // ---- pack P hi/lo as A-fragments ----
        uint32_t ph[4][4], pl[4][4];
        #pragma unroll
        for (int kc = 0; kc < 4; ++kc) {
            int n0t = 2 * kc, n1t = 2 * kc + 1;
            ph[kc][0] = pack_hi2(s[n0t][0], s[n0t][1]);
            pl[kc][0] = pack_lo2(s[n0t][0], s[n0t][1], ph[kc][0]);
            ph[kc][1] = pack_hi2(s[n0t][2], s[n0t][3]);
            pl[kc][1] = pack_lo2(s[n0t][2], s[n0t][3], ph[kc][1]);
            ph[kc][2] = pack_hi2(s[n1t][0], s[n1t][1]);
            pl[kc][2] = pack_lo2(s[n1t][0], s[n1t][1], ph[kc][2]);
            ph[kc][3] = pack_hi2(s[n1t][2], s[n1t][3]);
            pl[kc][3] = pack_lo2(s[n1t][2], s[n1t][3], ph[kc][3]);
        }

        // ---- O += P V (3-term split), 8-reg V live set ----
        #pragma unroll
        for (int kc = 0; kc < 4; ++kc) {
            #pragma unroll
            for (int dg = 0; dg < 4; ++dg) {
                uint32_t off = cs + (uint32_t)((kc * 16 + vkey) * ATS + (dg * 16 + vd) * 2);
                uint32_t vh[4], vl[4];
                ldsm4t(vh, sb + AV_HI + off);
                ldsm4t(vl, sb + AV_LO + off);
                int nt0 = 2 * dg, nt1 = 2 * dg + 1;
                mma16816(o[nt0], ph[kc], vh[0], vh[1]);
                mma16816(o[nt0], ph[kc], vl[0], vl[1]);
                mma16816(o[nt0], pl[kc], vh[0], vh[1]);
                mma16816(o[nt1], ph[kc], vh[2], vh[3]);
                mma16816(o[nt1], ph[kc], vl[2], vl[3]);
                mma16816(o[nt1], pl[kc], vh[2], vh[3]);
            }
        }
        __syncthreads();
    }

    // ---- normalize + emit bf16 hi/lo split ----
    float inv0 = 1.0f / l0r, inv1 = 1.0f / l1r;
    size_t row0 = (size_t)(b * SS + q0 + wq + gid) * EE + h * DD;
    size_t row1 = row0 + 8 * EE;
    #pragma unroll
    for (int nt = 0; nt < 8; ++nt) {
        int col = nt * 8 + tig * 2;
        float v0 = o[nt][0] * inv0, v1 = o[nt][1] * inv0;
        float v2 = o[nt][2] * inv1, v3 = o[nt][3] * inv1;
        uint32_t h0 = pack_hi2(v0, v1);
        uint32_t l0 = pack_lo2(v0, v1, h0);
        uint32_t h1 = pack_hi2(v2, v3);
        uint32_t l1 = pack_lo2(v2, v3, h1);
        *(uint32_t*)&g_AThi[row0 + col] = h0;
        *(uint32_t*)&g_ATlo[row0 + col] = l0;
        *(uint32_t*)&g_AThi[row1 + col] = h1;
        *(uint32_t*)&g_ATlo[row1 + col] = l1;
    }
}

// ---------------- launch ----------------
extern "C" void kernel_launch(void* const* d_in, const int* in_sizes, int n_in,
                              void* d_out, int out_size) {
    const float* query     = (const float*)d_in[0];
    const float* attn_bias = (const float*)d_in[3];
    const void*  kpm       = d_in[4];
    const float* attn_mask = (const float*)d_in[5];
    const float* Wq = (const float*)d_in[9];
    const float* bq = (const float*)d_in[10];
    const float* Wk = (const float*)d_in[11];
    const float* bk = (const float*)d_in[12];
    const float* Wv = (const float*)d_in[13];
    const float* bv = (const float*)d_in[14];
    const float* Wo = (const float*)d_in[15];
    const float* bo = (const float*)d_in[16];
    float* out = (float*)d_out;

    __nv_bfloat16 *gXhi, *gXlo, *gQhi, *gQlo, *gKhi, *gKlo, *gVhi, *gVlo,
                  *gAThi, *gATlo, *gWhi, *gWlo;
    cudaGetSymbolAddress((void**)&gXhi, g_Xhi);
    cudaGetSymbolAddress((void**)&gXlo, g_Xlo);
    cudaGetSymbolAddress((void**)&gQhi, g_Qhi);
    cudaGetSymbolAddress((void**)&gQlo, g_Qlo);
    cudaGetSymbolAddress((void**)&gKhi, g_Khi);
    cudaGetSymbolAddress((void**)&gKlo, g_Klo);
    cudaGetSymbolAddress((void**)&gVhi, g_Vhi);
    cudaGetSymbolAddress((void**)&gVlo, g_Vlo);
    cudaGetSymbolAddress((void**)&gAThi, g_AThi);
    cudaGetSymbolAddress((void**)&gATlo, g_ATlo);
    cudaGetSymbolAddress((void**)&gWhi, g_Whi);
    cudaGetSymbolAddress((void**)&gWlo, g_Wlo);

    cudaFuncSetAttribute(gemm_mma_kernel<true>,
                         cudaFuncAttributeMaxDynamicSharedMemorySize, GEMM_SMEM);
    cudaFuncSetAttribute(gemm_mma_kernel<false>,
                         cudaFuncAttributeMaxDynamicSharedMemorySize, GEMM_SMEM);
    cudaFuncSetAttribute(attention_mma_kernel,
                         cudaFuncAttributeMaxDynamicSharedMemorySize, ATT_SMEM);

    const int nq4 = BB * SS * EE / 4;
    const int nw4 = EE * EE / 4;
    split_kernel<<<(nq4 + 255) / 256, 256>>>(query, gXhi, gXlo, nq4);
    split_kernel<<<(nw4 + 255) / 256, 256>>>(Wq, gWhi + 0 * (size_t)EE * EE, gWlo + 0 * (size_t)EE * EE, nw4);
    split_kernel<<<(nw4 + 255) / 256, 256>>>(Wk, gWhi + 1 * (size_t)EE * EE, gWlo + 1 * (size_t)EE * EE, nw4);
    split_kernel<<<(nw4 + 255) / 256, 256>>>(Wv, gWhi + 2 * (size_t)EE * EE, gWlo + 2 * (size_t)EE * EE, nw4);
    split_kernel<<<(nw4 + 255) / 256, 256>>>(Wo, gWhi + 3 * (size_t)EE * EE, gWlo + 3 * (size_t)EE * EE, nw4);

    detect_mask_kernel<<<1, 256>>>(kpm);
    expand_mask_kernel<<<(BB * SS + 255) / 256, 256>>>(kpm);

    dim3 ggrid(EE / 128, BB * SS / 128);   // (8, 64)
    const float scaling = 0.125f;          // D^-0.5

    gemm_mma_kernel<true><<<ggrid, 256, GEMM_SMEM>>>(gXhi, gXlo,
        gWhi + 0 * (size_t)EE * EE, gWlo + 0 * (size_t)EE * EE, bq,
        nullptr, gQhi, gQlo, scaling);
    gemm_mma_kernel<true><<<ggrid, 256, GEMM_SMEM>>>(gXhi, gXlo,
        gWhi + 1 * (size_t)EE * EE, gWlo + 1 * (size_t)EE * EE, bk,
        nullptr, gKhi, gKlo, 1.0f);
    gemm_mma_kernel<true><<<ggrid, 256, GEMM_SMEM>>>(gXhi, gXlo,
        gWhi + 2 * (size_t)EE * EE, gWlo + 2 * (size_t)EE * EE, bv,
        nullptr, gVhi, gVlo, 1.0f);

    attention_mma_kernel<<<dim3(SS / 128, BB * HH), 256, ATT_SMEM>>>(attn_bias, attn_mask);

    gemm_mma_kernel<false><<<ggrid, 256, GEMM_SMEM>>>(gAThi, gATlo,
        gWhi + 3 * (size_t)EE * EE, gWlo + 3 * (size_t)EE * EE, bo,
        out, nullptr, nullptr, 1.0f);
}